// round 12
// baseline (speedup 1.0000x reference)
#include <cuda_runtime.h>
#include <cuda_fp16.h>
#include <cstdint>
#include <math.h>

#define N_NODES 50000
#define N_EDGES 500000
#define HID 256
#define LAYERS 15

// ---------------------------------------------------------------- scratch
__device__ float    g_h   [(size_t)N_NODES * HID];    // fp32 residual carry
__device__ uint32_t g_hh  [(size_t)N_NODES * 128];    // h as half2
__device__ uint32_t g_outh[(size_t)N_NODES * 128];    // pre-BN out as half2
__device__ uint32_t g_uv  [(size_t)N_NODES * 256];    // U|V per node (half2)
__device__ float    g_statsf[LAYERS * 512];           // per-layer BN sum/sumsq
// fp16 weights
__device__ uint32_t g_Wrel16 [LAYERS * 256 * 128];
__device__ uint32_t g_Wroot16[LAYERS * 256 * 128];
__device__ uint32_t g_W116[256 * 256];
__device__ uint32_t g_W216[256 * 128];
// CSR
__device__ int g_deg[N_NODES];
__device__ int g_off[N_NODES + 1];
__device__ int g_pos[N_NODES];
__device__ int g_srcs[N_EDGES];
__device__ int g_bsum[64];
__device__ int g_bsum2[64];

// ---------------------------------------------------------------- helpers
__device__ __forceinline__ uint32_t pack_h2(float x, float y) {
    __half2 h = __float22half2_rn(make_float2(x, y));
    return *(uint32_t*)&h;
}
__device__ __forceinline__ float2 unpack_h2(uint32_t u) {
    return __half22float2(*(__half2*)&u);
}
__device__ __forceinline__ void mma16(float* c, uint32_t a0, uint32_t a1,
                                      uint32_t a2, uint32_t a3,
                                      uint32_t b0, uint32_t b1) {
    asm volatile(
        "mma.sync.aligned.m16n8k16.row.col.f32.f16.f16.f32 "
        "{%0,%1,%2,%3}, {%4,%5,%6,%7}, {%8,%9}, {%0,%1,%2,%3};"
        : "+f"(c[0]), "+f"(c[1]), "+f"(c[2]), "+f"(c[3])
        : "r"(a0), "r"(a1), "r"(a2), "r"(a3), "r"(b0), "r"(b1));
}

// smem (half2 units):  A2[k2 8][row 128]  B2[k2 8][col 256], strides ≡ 8 mod 32
#define ASTR2 136
#define BSTR2 264
#define ASLAB (8 * ASTR2)              // 1088
#define BSLAB (8 * BSTR2)              // 2112
#define STAGE (ASLAB + BSLAB)          // 3200 uints (one 16-K slab A+B)
#define SCR_STR 132                    // gather scratch row stride (uint32)
#define NSMEM ((4 * STAGE + 128 * SCR_STR) * 4)   // 118784 B
#define UVSMEM (4 * STAGE * 4)         // 51200 B
#define SL 1096                        // z1 slab stride (padded: conflict-free fill)
#define Z1U2 (16 * SL)                 // 17536
#define ESMEM ((Z1U2 + 4 * BSLAB) * 4) // 103936 B

__device__ __forceinline__ void store_slab(uint32_t* As, uint32_t* Bs, int am, int k2,
                                           uint2 ra, uint2 rb0, uint2 rb1) {
    As[(k2 + 0) * ASTR2 + am] = ra.x;
    As[(k2 + 1) * ASTR2 + am] = ra.y;
    Bs[(k2 + 0) * BSTR2 + am] = rb0.x;
    Bs[(k2 + 1) * BSTR2 + am] = rb0.y;
    Bs[(k2 + 0) * BSTR2 + am + 128] = rb1.x;
    Bs[(k2 + 1) * BSTR2 + am + 128] = rb1.y;
}
__device__ __forceinline__ void store_slab_b(uint32_t* Bs, int am, int k2,
                                             uint2 rb0, uint2 rb1) {
    Bs[(k2 + 0) * BSTR2 + am] = rb0.x;
    Bs[(k2 + 1) * BSTR2 + am] = rb0.y;
    Bs[(k2 + 0) * BSTR2 + am + 128] = rb1.x;
    Bs[(k2 + 1) * BSTR2 + am + 128] = rb1.y;
}

__device__ __forceinline__ void mma_slab(const uint32_t* As, const uint32_t* Bs,
                                         int wm, int wn, int lane,
                                         float c[2][8][4]) {
    int g = lane >> 2, t = lane & 3;
    uint32_t b0[8], b1[8];
#pragma unroll
    for (int nt = 0; nt < 8; nt++) {
        int C = wn * 64 + nt * 8 + g;
        b0[nt] = Bs[t * BSTR2 + C];
        b1[nt] = Bs[(t + 4) * BSTR2 + C];
    }
#pragma unroll
    for (int mt = 0; mt < 2; mt++) {
        int R = wm * 32 + mt * 16 + g;
        uint32_t a0 = As[t * ASTR2 + R];
        uint32_t a1 = As[t * ASTR2 + R + 8];
        uint32_t a2 = As[(t + 4) * ASTR2 + R];
        uint32_t a3 = As[(t + 4) * ASTR2 + R + 8];
#pragma unroll
        for (int nt = 0; nt < 8; nt++)
            mma16(c[mt][nt], a0, a1, a2, a3, b0[nt], b1[nt]);
    }
}

// ---------------------------------------------------------------- small kernels
__global__ void k_cvt_weights(const float* __restrict__ Wrel,
                              const float* __restrict__ Wroot,
                              const float* __restrict__ W1,
                              const float* __restrict__ W2) {
    const int NREL = LAYERS * 256 * 128;
    const int NW1 = 256 * 256;
    const int NW2 = 256 * 128;
    int i = blockIdx.x * blockDim.x + threadIdx.x;
    if (i < LAYERS * 512) g_statsf[i] = 0.f;
    if (i < NREL) {
        g_Wrel16[i] = pack_h2(Wrel[2 * i], Wrel[2 * i + 1]);
        g_Wroot16[i] = pack_h2(Wroot[2 * i], Wroot[2 * i + 1]);
    } else {
        int j = i - NREL;
        if (j < NW1) g_W116[j] = pack_h2(W1[2 * j], W1[2 * j + 1]);
        else if (j - NW1 < NW2) {
            int k = j - NW1;
            g_W216[k] = pack_h2(W2[2 * k], W2[2 * k + 1]);
        }
    }
}

__global__ void k_input_fc(const float* __restrict__ x, const float* __restrict__ Win) {
    int idx = blockIdx.x * blockDim.x + threadIdx.x;   // half2 units
    if (idx < N_NODES) g_deg[idx] = 0;
    if (idx >= N_NODES * 128) return;
    int node = idx >> 7, c0 = (idx & 127) * 2;
    float x0 = x[node * 2], x1 = x[node * 2 + 1];
    float h0 = x0 * Win[c0 * 2] + x1 * Win[c0 * 2 + 1];
    float h1 = x0 * Win[c0 * 2 + 2] + x1 * Win[c0 * 2 + 3];
    ((float2*)g_h)[idx] = make_float2(h0, h1);
    g_hh[idx] = pack_h2(h0, h1);
}

__global__ void k_csr_count(const int* __restrict__ ei) {
    int e = blockIdx.x * blockDim.x + threadIdx.x;
    if (e >= N_EDGES) return;
    atomicAdd(&g_deg[__ldg(ei + N_EDGES + e)], 1);
}

// multi-block scan: block-local exclusive + block sums
__global__ void k_scan1() {
    __shared__ int wsum[32];
    int tid = threadIdx.x, lane = tid & 31, wid = tid >> 5;
    int i = blockIdx.x * 1024 + tid;
    int v = (i < N_NODES) ? g_deg[i] : 0;
    int x = v;
#pragma unroll
    for (int d = 1; d < 32; d <<= 1) {
        int y = __shfl_up_sync(0xffffffffu, x, d);
        if (lane >= d) x += y;
    }
    if (lane == 31) wsum[wid] = x;
    __syncthreads();
    if (wid == 0) {
        int w = wsum[lane];
#pragma unroll
        for (int d = 1; d < 32; d <<= 1) {
            int y = __shfl_up_sync(0xffffffffu, w, d);
            if (lane >= d) w += y;
        }
        wsum[lane] = w;
    }
    __syncthreads();
    int incl = x + (wid > 0 ? wsum[wid - 1] : 0);
    if (i < N_NODES) g_off[i] = incl - v;       // block-local exclusive
    if (tid == 0) g_bsum[blockIdx.x] = wsum[31];
}

__global__ void k_scan2(int nblk) {
    if (threadIdx.x == 0) {
        int acc = 0;
        for (int b = 0; b < nblk; b++) { g_bsum2[b] = acc; acc += g_bsum[b]; }
        g_off[N_NODES] = acc;
    }
}

__global__ void k_scan3() {
    int i = blockIdx.x * blockDim.x + threadIdx.x;
    if (i >= N_NODES) return;
    int o = g_off[i] + g_bsum2[i >> 10];
    g_off[i] = o;
    g_pos[i] = o;
}

__global__ void k_csr_fill(const int* __restrict__ ei) {
    int e = blockIdx.x * blockDim.x + threadIdx.x;
    if (e >= N_EDGES) return;
    int d = __ldg(ei + N_EDGES + e);
    int p = atomicAdd(&g_pos[d], 1);
    g_srcs[p] = __ldg(ei + e);
}

// ---- BN finalize + apply fused ----
__global__ void k_bn_apply(int layer, const float* __restrict__ gm,
                           const float* __restrict__ bt) {
    __shared__ float ssc[HID], ssh[HID];
    const float* stats = g_statsf + (size_t)layer * 512;
    int tid = threadIdx.x;
    if (tid < HID) {
        float mean = stats[tid] * (1.f / N_NODES);
        float var  = stats[HID + tid] * (1.f / N_NODES) - mean * mean;
        float rstd = rsqrtf(var + 1e-5f);
        float sc = rstd * __ldg(gm + tid);
        ssc[tid] = sc;
        ssh[tid] = __ldg(bt + tid) - mean * sc;
    }
    __syncthreads();
    int idx = blockIdx.x * blockDim.x + tid;
    if (idx >= N_NODES * 128) return;
    int c0 = (idx & 127) * 2;
    float2 o = unpack_h2(g_outh[idx]);
    float2 hv = ((float2*)g_h)[idx];
    hv.x += fmaxf(fmaf(o.x, ssc[c0], ssh[c0]), 0.f);
    hv.y += fmaxf(fmaf(o.y, ssc[c0 + 1], ssh[c0 + 1]), 0.f);
    ((float2*)g_h)[idx] = hv;
    g_hh[idx] = pack_h2(hv.x, hv.y);
}

// =================================================================
// node layer: phase 0 gathers agg into smem, BK=32 fp16 GEMM,
// fused BN stats epilogue.  (proven R10 structure)
// =================================================================
__global__ void __launch_bounds__(512, 1)
k_gemm_node(int layer, const float* __restrict__ br) {
    extern __shared__ uint32_t sm[];
    uint32_t* bufs = sm;
    uint32_t* scr  = sm + 4 * STAGE;
    int tid = threadIdx.x;
    int bm = blockIdx.x * 128;
    int lane = tid & 31, lq = lane >> 2, lr = lane & 3;
    int wid = tid >> 5, wm = wid & 3, wn = wid >> 2;
    int am = tid >> 2, aks = (tid & 3) * 4;
    int k2 = aks >> 1;
    int gr = bm + am;
    bool arow = gr < N_NODES;
    const uint32_t* Wr = g_Wrel16 + (size_t)layer * 256 * 128;
    const uint32_t* Wo = g_Wroot16 + (size_t)layer * 256 * 128;
    float* stats = g_statsf + (size_t)layer * 512;

    // ---- phase 0: gather ----
    {
        const uint4* hp = (const uint4*)g_hh;
        for (int i = 0; i < 8; i++) {
            int row = wid * 8 + i;
            int node = bm + row;
            float acc[8] = {};
            if (node < N_NODES) {
                int beg = g_off[node], end = g_off[node + 1];
                int t = beg;
                for (; t + 1 < end; t += 2) {
                    int s0 = __ldg(&g_srcs[t]);
                    int s1 = __ldg(&g_srcs[t + 1]);
                    uint4 v0 = __ldg(hp + (size_t)s0 * 32 + lane);
                    uint4 v1 = __ldg(hp + (size_t)s1 * 32 + lane);
                    float2 f;
                    f = unpack_h2(v0.x); acc[0] += f.x; acc[1] += f.y;
                    f = unpack_h2(v0.y); acc[2] += f.x; acc[3] += f.y;
                    f = unpack_h2(v0.z); acc[4] += f.x; acc[5] += f.y;
                    f = unpack_h2(v0.w); acc[6] += f.x; acc[7] += f.y;
                    f = unpack_h2(v1.x); acc[0] += f.x; acc[1] += f.y;
                    f = unpack_h2(v1.y); acc[2] += f.x; acc[3] += f.y;
                    f = unpack_h2(v1.z); acc[4] += f.x; acc[5] += f.y;
                    f = unpack_h2(v1.w); acc[6] += f.x; acc[7] += f.y;
                }
                if (t < end) {
                    int s0 = __ldg(&g_srcs[t]);
                    uint4 v0 = __ldg(hp + (size_t)s0 * 32 + lane);
                    float2 f;
                    f = unpack_h2(v0.x); acc[0] += f.x; acc[1] += f.y;
                    f = unpack_h2(v0.y); acc[2] += f.x; acc[3] += f.y;
                    f = unpack_h2(v0.z); acc[4] += f.x; acc[5] += f.y;
                    f = unpack_h2(v0.w); acc[6] += f.x; acc[7] += f.y;
                }
            }
            uint4 o;
            o.x = pack_h2(acc[0], acc[1]);
            o.y = pack_h2(acc[2], acc[3]);
            o.z = pack_h2(acc[4], acc[5]);
            o.w = pack_h2(acc[6], acc[7]);
            *(uint4*)(scr + row * SCR_STR + lane * 4) = o;
        }
    }
    __syncthreads();

    // ---- mainloop: 16 stages x 32 K ----
    float c[2][8][4] = {};
    uint2 ra[2], rb0[2], rb1[2];
#pragma unroll
    for (int j = 0; j < 2; j++) {
        int hoff = j * 16 + aks;
        int kc2 = hoff >> 2;
        ra[j] = *(const uint2*)(scr + am * SCR_STR + (hoff >> 1));
        rb0[j] = __ldg((const uint2*)(Wr + (size_t)am * 128) + kc2);
        rb1[j] = __ldg((const uint2*)(Wr + (size_t)(am + 128) * 128) + kc2);
    }
    for (int st = 0; st < 16; st++) {
        int b = st & 1;
        uint32_t* s0 = bufs + b * 2 * STAGE;
        uint32_t* s1 = s0 + STAGE;
        store_slab(s0, s0 + ASLAB, am, k2, ra[0], rb0[0], rb1[0]);
        store_slab(s1, s1 + ASLAB, am, k2, ra[1], rb0[1], rb1[1]);
        uint2 na[2] = {ra[0], ra[1]}, nb0[2] = {rb0[0], rb0[1]}, nb1[2] = {rb1[0], rb1[1]};
        if (st < 15) {
#pragma unroll
            for (int j = 0; j < 2; j++) {
                int kk = 2 * st + 2 + j;
                int half = kk >> 4;
                int hoff = (kk & 15) * 16 + aks;
                int kc2 = hoff >> 2;
                if (half == 0) {
                    na[j] = *(const uint2*)(scr + am * SCR_STR + (hoff >> 1));
                    nb0[j] = __ldg((const uint2*)(Wr + (size_t)am * 128) + kc2);
                    nb1[j] = __ldg((const uint2*)(Wr + (size_t)(am + 128) * 128) + kc2);
                } else {
                    na[j] = arow ? __ldg((const uint2*)(g_hh + (size_t)gr * 128) + kc2)
                                 : make_uint2(0u, 0u);
                    nb0[j] = __ldg((const uint2*)(Wo + (size_t)am * 128) + kc2);
                    nb1[j] = __ldg((const uint2*)(Wo + (size_t)(am + 128) * 128) + kc2);
                }
            }
        }
        __syncthreads();
        mma_slab(s0, s0 + ASLAB, wm, wn, lane, c);
        mma_slab(s1, s1 + ASLAB, wm, wn, lane, c);
        ra[0] = na[0]; ra[1] = na[1];
        rb0[0] = nb0[0]; rb0[1] = nb0[1];
        rb1[0] = nb1[0]; rb1[1] = nb1[1];
    }

    // ---- epilogue ----
    float ps[8][2], pq[8][2];
#pragma unroll
    for (int nt = 0; nt < 8; nt++)
        ps[nt][0] = ps[nt][1] = pq[nt][0] = pq[nt][1] = 0.f;

#pragma unroll
    for (int mt = 0; mt < 2; mt++) {
        int row = bm + wm * 32 + mt * 16 + lq;
        bool v0 = row < N_NODES, v1 = (row + 8) < N_NODES;
#pragma unroll
        for (int nt = 0; nt < 8; nt++) {
            int col = wn * 64 + nt * 8 + lr * 2;
            float2 bb = __ldg((const float2*)(br + col));
            float o0 = c[mt][nt][0] + bb.x, o1 = c[mt][nt][1] + bb.y;
            float o2 = c[mt][nt][2] + bb.x, o3 = c[mt][nt][3] + bb.y;
            if (v0) {
                g_outh[(size_t)row * 128 + (col >> 1)] = pack_h2(o0, o1);
                ps[nt][0] += o0; pq[nt][0] += o0 * o0;
                ps[nt][1] += o1; pq[nt][1] += o1 * o1;
            }
            if (v1) {
                g_outh[(size_t)(row + 8) * 128 + (col >> 1)] = pack_h2(o2, o3);
                ps[nt][0] += o2; pq[nt][0] += o2 * o2;
                ps[nt][1] += o3; pq[nt][1] += o3 * o3;
            }
        }
    }
#pragma unroll
    for (int nt = 0; nt < 8; nt++)
#pragma unroll
        for (int u = 0; u < 2; u++) {
#pragma unroll
            for (int d = 4; d < 32; d <<= 1) {
                ps[nt][u] += __shfl_xor_sync(0xffffffffu, ps[nt][u], d);
                pq[nt][u] += __shfl_xor_sync(0xffffffffu, pq[nt][u], d);
            }
        }
    if (lq == 0) {
#pragma unroll
        for (int nt = 0; nt < 8; nt++) {
            int col = wn * 64 + nt * 8 + lr * 2;
            atomicAdd(&stats[col], ps[nt][0]);
            atomicAdd(&stats[col + 1], ps[nt][1]);
            atomicAdd(&stats[HID + col], pq[nt][0]);
            atomicAdd(&stats[HID + col + 1], pq[nt][1]);
        }
    }
}

// =================================================================
// UV precompute: U|V = h @ [W1a;W1b]^T ; grid (391, 2), ny: 0=U 1=V
// =================================================================
__global__ void __launch_bounds__(512, 1)
k_gemm_uv() {
    extern __shared__ uint32_t sm[];
    uint32_t* bufs = sm;
    int tid = threadIdx.x;
    int bm = blockIdx.x * 128;
    int ny = blockIdx.y;
    int lane = tid & 31, lq = lane >> 2, lr = lane & 3;
    int wid = tid >> 5, wm = wid & 3, wn = wid >> 2;
    int am = tid >> 2, aks = (tid & 3) * 4;
    int k2 = aks >> 1;
    int gr = bm + am;
    bool arow = gr < N_NODES;
    float c[2][8][4] = {};

    uint2 ra[2], rb0[2], rb1[2];
#pragma unroll
    for (int j = 0; j < 2; j++) {
        int kc2 = (j * 16 + aks) >> 2;
        ra[j] = arow ? __ldg((const uint2*)(g_hh + (size_t)gr * 128) + kc2)
                     : make_uint2(0u, 0u);
        rb0[j] = __ldg((const uint2*)(g_W116 + (size_t)am * 256) + ny * 64 + kc2);
        rb1[j] = __ldg((const uint2*)(g_W116 + (size_t)(am + 128) * 256) + ny * 64 + kc2);
    }
    for (int st = 0; st < 8; st++) {
        int b = st & 1;
        uint32_t* s0 = bufs + b * 2 * STAGE;
        uint32_t* s1 = s0 + STAGE;
        store_slab(s0, s0 + ASLAB, am, k2, ra[0], rb0[0], rb1[0]);
        store_slab(s1, s1 + ASLAB, am, k2, ra[1], rb0[1], rb1[1]);
        uint2 na[2] = {ra[0], ra[1]}, nb0[2] = {rb0[0], rb0[1]}, nb1[2] = {rb1[0], rb1[1]};
        if (st < 7) {
#pragma unroll
            for (int j = 0; j < 2; j++) {
                int kc2 = ((2 * st + 2 + j) * 16 + aks) >> 2;
                na[j] = arow ? __ldg((const uint2*)(g_hh + (size_t)gr * 128) + kc2)
                             : make_uint2(0u, 0u);
                nb0[j] = __ldg((const uint2*)(g_W116 + (size_t)am * 256) + ny * 64 + kc2);
                nb1[j] = __ldg((const uint2*)(g_W116 + (size_t)(am + 128) * 256) + ny * 64 + kc2);
            }
        }
        __syncthreads();
        mma_slab(s0, s0 + ASLAB, wm, wn, lane, c);
        mma_slab(s1, s1 + ASLAB, wm, wn, lane, c);
        ra[0] = na[0]; ra[1] = na[1];
        rb0[0] = nb0[0]; rb0[1] = nb0[1];
        rb1[0] = nb1[0]; rb1[1] = nb1[1];
    }
#pragma unroll
    for (int mt = 0; mt < 2; mt++) {
        int row = bm + wm * 32 + mt * 16 + lq;
#pragma unroll
        for (int nt = 0; nt < 8; nt++) {
            int col = wn * 64 + nt * 8 + lr * 2;
            if (row < N_NODES)
                g_uv[(size_t)row * 256 + ny * 128 + (col >> 1)] =
                    pack_h2(c[mt][nt][0], c[mt][nt][1]);
            if (row + 8 < N_NODES)
                g_uv[(size_t)(row + 8) * 256 + ny * 128 + (col >> 1)] =
                    pack_h2(c[mt][nt][2], c[mt][nt][3]);
        }
    }
}

// =================================================================
// fused edge MLP: z1 = relu(U[src]+V[dst]+b1) assembled in smem,
// then z1 @ W2^T, dot w3, sigmoid.
// =================================================================
__global__ void __launch_bounds__(512, 1)
k_edge_fused(const int* __restrict__ ei, const float* __restrict__ b1,
             const float* __restrict__ b2, const float* __restrict__ W3,
             const float* __restrict__ b3, float* __restrict__ dout) {
    extern __shared__ uint32_t sm[];
    uint32_t* z1sm = sm;                 // 16 slabs x SL
    uint32_t* bufs = sm + Z1U2;          // 4 x BSLAB
    __shared__ float sred[4][128];
    int tid = threadIdx.x;
    int bm = blockIdx.x * 128;
    int lane = tid & 31, lq = lane >> 2, lr = lane & 3;
    int wid = tid >> 5, wm = wid & 3, wn = wid >> 2;
    int am = tid >> 2, aks = (tid & 3) * 4;
    int k2 = aks >> 1;

    // ---- stage 0: assemble z1 in fragment layout ----
    {
        int row = tid >> 2, sub = tid & 3;
        int e = bm + row;
        bool val = e < N_EDGES;
        int nsrc = val ? __ldg(ei + e) : 0;
        int ndst = val ? __ldg(ei + N_EDGES + e) : 0;
        const uint4* up = (const uint4*)(g_uv + (size_t)nsrc * 256);
        const uint4* vp = (const uint4*)(g_uv + (size_t)ndst * 256 + 128);
#pragma unroll
        for (int q = 0; q < 4; q++) {
            int c2b = q * 32 + sub * 8;
            uint4 u0 = __ldg(up + (c2b >> 2));
            uint4 u1 = __ldg(up + (c2b >> 2) + 1);
            uint4 v0 = __ldg(vp + (c2b >> 2));
            uint4 v1 = __ldg(vp + (c2b >> 2) + 1);
            uint32_t uu[8] = {u0.x, u0.y, u0.z, u0.w, u1.x, u1.y, u1.z, u1.w};
            uint32_t vv[8] = {v0.x, v0.y, v0.z, v0.w, v1.x, v1.y, v1.z, v1.w};
            uint32_t* dst = z1sm + (q * 4 + sub) * SL + row;
#pragma unroll
            for (int j = 0; j < 8; j++) {
                int c2 = c2b + j;
                float2 fu = unpack_h2(uu[j]);
                float2 fv = unpack_h2(vv[j]);
                float2 bb = __ldg((const float2*)b1 + c2);
                dst[j * ASTR2] = pack_h2(fmaxf(fu.x + fv.x + bb.x, 0.f),
                                         fmaxf(fu.y + fv.y + bb.y, 0.f));
            }
        }
    }
    __syncthreads();

    // ---- stage 2: z1 @ W2^T (BK=32, B double-buffered) ----
    float c[2][8][4] = {};
    uint2 qb0[2], qb1[2];
#pragma unroll
    for (int j = 0; j < 2; j++) {
        int kc2 = (j * 16 + aks) >> 2;
        qb0[j] = __ldg((const uint2*)(g_W216 + (size_t)am * 128) + kc2);
        qb1[j] = __ldg((const uint2*)(g_W216 + (size_t)(am + 128) * 128) + kc2);
    }
    for (int st = 0; st < 8; st++) {
        int b = st & 1;
        uint32_t* B0 = bufs + b * 2 * BSLAB;
        uint32_t* B1 = B0 + BSLAB;
        store_slab_b(B0, am, k2, qb0[0], qb1[0]);
        store_slab_b(B1, am, k2, qb0[1], qb1[1]);
        uint2 n0[2] = {qb0[0], qb0[1]}, n1[2] = {qb1[0], qb1[1]};
        if (st < 7) {
#pragma unroll
            for (int j = 0; j < 2; j++) {
                int kc2 = ((2 * st + 2 + j) * 16 + aks) >> 2;
                n0[j] = __ldg((const uint2*)(g_W216 + (size_t)am * 128) + kc2);
                n1[j] = __ldg((const uint2*)(g_W216 + (size_t)(am + 128) * 128) + kc2);
            }
        }
        __syncthreads();
        mma_slab(z1sm + (2 * st) * SL, B0, wm, wn, lane, c);
        mma_slab(z1sm + (2 * st + 1) * SL, B1, wm, wn, lane, c);
        qb0[0] = n0[0]; qb0[1] = n0[1];
        qb1[0] = n1[0]; qb1[1] = n1[1];
    }

#pragma unroll
    for (int mt = 0; mt < 2; mt++) {
        float p0 = 0.f, p1 = 0.f;
#pragma unroll
        for (int nt = 0; nt < 8; nt++) {
            int col = wn * 64 + nt * 8 + lr * 2;
            float2 bb = __ldg((const float2*)(b2 + col));
            float2 ww = __ldg((const float2*)(W3 + col));
            p0 = fmaf(fmaxf(c[mt][nt][0] + bb.x, 0.f), ww.x, p0);
            p0 = fmaf(fmaxf(c[mt][nt][1] + bb.y, 0.f), ww.y, p0);
            p1 = fmaf(fmaxf(c[mt][nt][2] + bb.x, 0.f), ww.x, p1);
            p1 = fmaf(fmaxf(c[mt][nt][3] + bb.y, 0.f), ww.y, p1);
        }
        p0 += __shfl_xor_sync(0xffffffffu, p0, 1);
        p0 += __shfl_xor_sync(0xffffffffu, p0, 2);
        p1 += __shfl_xor_sync(0xffffffffu, p1, 1);
        p1 += __shfl_xor_sync(0xffffffffu, p1, 2);
        if (lr == 0) {
            sred[wn][wm * 32 + mt * 16 + lq] = p0;
            sred[wn][wm * 32 + mt * 16 + lq + 8] = p1;
        }
    }
    __syncthreads();
    if (tid < 128) {
        int gr = bm + tid;
        if (gr < N_EDGES) {
            float s = sred[0][tid] + sred[1][tid] + sred[2][tid] + sred[3][tid] + __ldg(b3);
            dout[gr] = 1.f / (1.f + expf(-s));
        }
    }
}

// ---------------------------------------------------------------- launch
extern "C" void kernel_launch(void* const* d_in, const int* in_sizes, int n_in,
                              void* d_out, int out_size) {
    const float* x     = (const float*)d_in[0];
    const int*   ei    = (const int*)  d_in[1];
    const float* Win   = (const float*)d_in[2];
    const float* Wrel  = (const float*)d_in[3];
    const float* brel  = (const float*)d_in[4];
    const float* Wroot = (const float*)d_in[5];
    const float* gamma = (const float*)d_in[6];
    const float* beta  = (const float*)d_in[7];
    const float* W1    = (const float*)d_in[8];
    const float* b1    = (const float*)d_in[9];
    const float* W2    = (const float*)d_in[10];
    const float* b2    = (const float*)d_in[11];
    const float* W3    = (const float*)d_in[12];
    const float* b3    = (const float*)d_in[13];
    float* out = (float*)d_out;

    cudaFuncSetAttribute(k_gemm_node, cudaFuncAttributeMaxDynamicSharedMemorySize, NSMEM);
    cudaFuncSetAttribute(k_gemm_uv,   cudaFuncAttributeMaxDynamicSharedMemorySize, UVSMEM);
    cudaFuncSetAttribute(k_edge_fused, cudaFuncAttributeMaxDynamicSharedMemorySize, ESMEM);

    int ncvt = LAYERS * 256 * 128 + 256 * 256 + 256 * 128;
    k_cvt_weights<<<(ncvt + 255) / 256, 256>>>(Wrel, Wroot, W1, W2);
    k_input_fc<<<(N_NODES * 128 + 255) / 256, 256>>>(x, Win);
    k_csr_count<<<(N_EDGES + 255) / 256, 256>>>(ei);
    int nblk = (N_NODES + 1023) / 1024;   // 49
    k_scan1<<<nblk, 1024>>>();
    k_scan2<<<1, 32>>>(nblk);
    k_scan3<<<(N_NODES + 255) / 256, 256>>>();
    k_csr_fill<<<(N_EDGES + 255) / 256, 256>>>(ei);

    int node_grid = (N_NODES + 127) / 128;     // 391
    for (int l = 0; l < LAYERS; l++) {
        k_gemm_node<<<node_grid, 512, NSMEM>>>(l, brel + (size_t)l * HID);
        k_bn_apply<<<(N_NODES * 128 + 255) / 256, 256>>>(
            l, gamma + (size_t)l * HID, beta + (size_t)l * HID);
    }

    dim3 uv_grid(node_grid, 2);
    k_gemm_uv<<<uv_grid, 512, UVSMEM>>>();
    int edge_grid = (N_EDGES + 127) / 128;     // 3907
    k_edge_fused<<<edge_grid, 512, ESMEM>>>(ei, b1, b2, W3, b3, out);
}

// round 13
// speedup vs baseline: 1.4402x; 1.4402x over previous
#include <cuda_runtime.h>
#include <cuda_fp16.h>
#include <cstdint>
#include <math.h>

#define N_NODES 50000
#define N_EDGES 500000
#define HID 256
#define LAYERS 15

// ---------------------------------------------------------------- scratch
__device__ float    g_h   [(size_t)N_NODES * HID];    // fp32 residual carry
__device__ uint32_t g_hh  [(size_t)N_NODES * 128];    // h as half2
__device__ uint32_t g_outh[(size_t)N_NODES * 128];    // pre-BN out as half2
__device__ uint32_t g_uv  [(size_t)N_NODES * 256];    // U|V per node (half2)
__device__ float    g_statsf[LAYERS * 512];           // per-layer BN sum/sumsq
// fp16 weights
__device__ uint32_t g_Wrel16 [LAYERS * 256 * 128];
__device__ uint32_t g_Wroot16[LAYERS * 256 * 128];
__device__ uint32_t g_W116[256 * 256];
__device__ uint32_t g_W216[256 * 128];
// CSR
__device__ int g_deg[N_NODES];
__device__ int g_off[N_NODES + 1];
__device__ int g_pos[N_NODES];
__device__ int g_srcs[N_EDGES];
__device__ int g_bsum[64];
__device__ int g_bsum2[64];

// ---------------------------------------------------------------- helpers
__device__ __forceinline__ uint32_t pack_h2(float x, float y) {
    __half2 h = __float22half2_rn(make_float2(x, y));
    return *(uint32_t*)&h;
}
__device__ __forceinline__ float2 unpack_h2(uint32_t u) {
    return __half22float2(*(__half2*)&u);
}
__device__ __forceinline__ void mma16(float* c, uint32_t a0, uint32_t a1,
                                      uint32_t a2, uint32_t a3,
                                      uint32_t b0, uint32_t b1) {
    asm volatile(
        "mma.sync.aligned.m16n8k16.row.col.f32.f16.f16.f32 "
        "{%0,%1,%2,%3}, {%4,%5,%6,%7}, {%8,%9}, {%0,%1,%2,%3};"
        : "+f"(c[0]), "+f"(c[1]), "+f"(c[2]), "+f"(c[3])
        : "r"(a0), "r"(a1), "r"(a2), "r"(a3), "r"(b0), "r"(b1));
}

// smem (half2 units):  A2[k2 8][row 128]  B2[k2 8][col 256], strides ≡ 8 mod 32
#define ASTR2 136
#define BSTR2 264
#define ASLAB (8 * ASTR2)              // 1088
#define BSLAB (8 * BSTR2)              // 2112
#define STAGE (ASLAB + BSLAB)          // 3200 uints (one 16-K slab A+B)
#define SCR_STR 132                    // gather scratch row stride (uint32)
#define NSMEM ((4 * STAGE + 128 * SCR_STR) * 4)   // 118784 B
#define UVSMEM (4 * STAGE * 4)         // 51200 B
#define SL 1096                        // z1 slab stride (padded: conflict-free fill)
#define Z1U2 (16 * SL)                 // 17536
#define ESMEM ((Z1U2 + 4 * BSLAB) * 4) // 103936 B

__device__ __forceinline__ void store_slab(uint32_t* As, uint32_t* Bs, int am, int k2,
                                           uint2 ra, uint2 rb0, uint2 rb1) {
    As[(k2 + 0) * ASTR2 + am] = ra.x;
    As[(k2 + 1) * ASTR2 + am] = ra.y;
    Bs[(k2 + 0) * BSTR2 + am] = rb0.x;
    Bs[(k2 + 1) * BSTR2 + am] = rb0.y;
    Bs[(k2 + 0) * BSTR2 + am + 128] = rb1.x;
    Bs[(k2 + 1) * BSTR2 + am + 128] = rb1.y;
}
__device__ __forceinline__ void store_slab_b(uint32_t* Bs, int am, int k2,
                                             uint2 rb0, uint2 rb1) {
    Bs[(k2 + 0) * BSTR2 + am] = rb0.x;
    Bs[(k2 + 1) * BSTR2 + am] = rb0.y;
    Bs[(k2 + 0) * BSTR2 + am + 128] = rb1.x;
    Bs[(k2 + 1) * BSTR2 + am + 128] = rb1.y;
}

__device__ __forceinline__ void mma_slab(const uint32_t* As, const uint32_t* Bs,
                                         int wm, int wn, int lane,
                                         float c[2][8][4]) {
    int g = lane >> 2, t = lane & 3;
    uint32_t b0[8], b1[8];
#pragma unroll
    for (int nt = 0; nt < 8; nt++) {
        int C = wn * 64 + nt * 8 + g;
        b0[nt] = Bs[t * BSTR2 + C];
        b1[nt] = Bs[(t + 4) * BSTR2 + C];
    }
#pragma unroll
    for (int mt = 0; mt < 2; mt++) {
        int R = wm * 32 + mt * 16 + g;
        uint32_t a0 = As[t * ASTR2 + R];
        uint32_t a1 = As[t * ASTR2 + R + 8];
        uint32_t a2 = As[(t + 4) * ASTR2 + R];
        uint32_t a3 = As[(t + 4) * ASTR2 + R + 8];
#pragma unroll
        for (int nt = 0; nt < 8; nt++)
            mma16(c[mt][nt], a0, a1, a2, a3, b0[nt], b1[nt]);
    }
}

// ---------------------------------------------------------------- small kernels
__global__ void k_cvt_weights(const float* __restrict__ Wrel,
                              const float* __restrict__ Wroot,
                              const float* __restrict__ W1,
                              const float* __restrict__ W2) {
    const int NREL = LAYERS * 256 * 128;
    const int NW1 = 256 * 256;
    const int NW2 = 256 * 128;
    int i = blockIdx.x * blockDim.x + threadIdx.x;
    if (i < LAYERS * 512) g_statsf[i] = 0.f;
    if (i < NREL) {
        g_Wrel16[i] = pack_h2(Wrel[2 * i], Wrel[2 * i + 1]);
        g_Wroot16[i] = pack_h2(Wroot[2 * i], Wroot[2 * i + 1]);
    } else {
        int j = i - NREL;
        if (j < NW1) g_W116[j] = pack_h2(W1[2 * j], W1[2 * j + 1]);
        else if (j - NW1 < NW2) {
            int k = j - NW1;
            g_W216[k] = pack_h2(W2[2 * k], W2[2 * k + 1]);
        }
    }
}

__global__ void k_input_fc(const float* __restrict__ x, const float* __restrict__ Win) {
    int idx = blockIdx.x * blockDim.x + threadIdx.x;   // half2 units
    if (idx < N_NODES) g_deg[idx] = 0;
    if (idx >= N_NODES * 128) return;
    int node = idx >> 7, c0 = (idx & 127) * 2;
    float x0 = x[node * 2], x1 = x[node * 2 + 1];
    float h0 = x0 * Win[c0 * 2] + x1 * Win[c0 * 2 + 1];
    float h1 = x0 * Win[c0 * 2 + 2] + x1 * Win[c0 * 2 + 3];
    ((float2*)g_h)[idx] = make_float2(h0, h1);
    g_hh[idx] = pack_h2(h0, h1);
}

__global__ void k_csr_count(const int* __restrict__ ei) {
    int e = blockIdx.x * blockDim.x + threadIdx.x;
    if (e >= N_EDGES) return;
    atomicAdd(&g_deg[__ldg(ei + N_EDGES + e)], 1);
}

// multi-block scan: block-local exclusive + block sums
__global__ void k_scan1() {
    __shared__ int wsum[32];
    int tid = threadIdx.x, lane = tid & 31, wid = tid >> 5;
    int i = blockIdx.x * 1024 + tid;
    int v = (i < N_NODES) ? g_deg[i] : 0;
    int x = v;
#pragma unroll
    for (int d = 1; d < 32; d <<= 1) {
        int y = __shfl_up_sync(0xffffffffu, x, d);
        if (lane >= d) x += y;
    }
    if (lane == 31) wsum[wid] = x;
    __syncthreads();
    if (wid == 0) {
        int w = wsum[lane];
#pragma unroll
        for (int d = 1; d < 32; d <<= 1) {
            int y = __shfl_up_sync(0xffffffffu, w, d);
            if (lane >= d) w += y;
        }
        wsum[lane] = w;
    }
    __syncthreads();
    int incl = x + (wid > 0 ? wsum[wid - 1] : 0);
    if (i < N_NODES) g_off[i] = incl - v;       // block-local exclusive
    if (tid == 0) g_bsum[blockIdx.x] = wsum[31];
}

__global__ void k_scan2(int nblk) {
    if (threadIdx.x == 0) {
        int acc = 0;
        for (int b = 0; b < nblk; b++) { g_bsum2[b] = acc; acc += g_bsum[b]; }
        g_off[N_NODES] = acc;
    }
}

__global__ void k_scan3() {
    int i = blockIdx.x * blockDim.x + threadIdx.x;
    if (i >= N_NODES) return;
    int o = g_off[i] + g_bsum2[i >> 10];
    g_off[i] = o;
    g_pos[i] = o;
}

__global__ void k_csr_fill(const int* __restrict__ ei) {
    int e = blockIdx.x * blockDim.x + threadIdx.x;
    if (e >= N_EDGES) return;
    int d = __ldg(ei + N_EDGES + e);
    int p = atomicAdd(&g_pos[d], 1);
    g_srcs[p] = __ldg(ei + e);
}

// ---- BN finalize + apply fused ----
__global__ void k_bn_apply(int layer, const float* __restrict__ gm,
                           const float* __restrict__ bt) {
    __shared__ float ssc[HID], ssh[HID];
    const float* stats = g_statsf + (size_t)layer * 512;
    int tid = threadIdx.x;
    if (tid < HID) {
        float mean = stats[tid] * (1.f / N_NODES);
        float var  = stats[HID + tid] * (1.f / N_NODES) - mean * mean;
        float rstd = rsqrtf(var + 1e-5f);
        float sc = rstd * __ldg(gm + tid);
        ssc[tid] = sc;
        ssh[tid] = __ldg(bt + tid) - mean * sc;
    }
    __syncthreads();
    int idx = blockIdx.x * blockDim.x + tid;
    if (idx >= N_NODES * 128) return;
    int c0 = (idx & 127) * 2;
    float2 o = unpack_h2(g_outh[idx]);
    float2 hv = ((float2*)g_h)[idx];
    hv.x += fmaxf(fmaf(o.x, ssc[c0], ssh[c0]), 0.f);
    hv.y += fmaxf(fmaf(o.y, ssc[c0 + 1], ssh[c0 + 1]), 0.f);
    ((float2*)g_h)[idx] = hv;
    g_hh[idx] = pack_h2(hv.x, hv.y);
}

// =================================================================
// node layer: phase 0 gathers agg into smem, BK=32 fp16 GEMM,
// fused BN stats epilogue.  (proven R10 structure)
// =================================================================
__global__ void __launch_bounds__(512, 1)
k_gemm_node(int layer, const float* __restrict__ br) {
    extern __shared__ uint32_t sm[];
    uint32_t* bufs = sm;
    uint32_t* scr  = sm + 4 * STAGE;
    int tid = threadIdx.x;
    int bm = blockIdx.x * 128;
    int lane = tid & 31, lq = lane >> 2, lr = lane & 3;
    int wid = tid >> 5, wm = wid & 3, wn = wid >> 2;
    int am = tid >> 2, aks = (tid & 3) * 4;
    int k2 = aks >> 1;
    int gr = bm + am;
    bool arow = gr < N_NODES;
    const uint32_t* Wr = g_Wrel16 + (size_t)layer * 256 * 128;
    const uint32_t* Wo = g_Wroot16 + (size_t)layer * 256 * 128;
    float* stats = g_statsf + (size_t)layer * 512;

    // ---- phase 0: gather ----
    {
        const uint4* hp = (const uint4*)g_hh;
        for (int i = 0; i < 8; i++) {
            int row = wid * 8 + i;
            int node = bm + row;
            float acc[8] = {};
            if (node < N_NODES) {
                int beg = g_off[node], end = g_off[node + 1];
                int t = beg;
                for (; t + 1 < end; t += 2) {
                    int s0 = __ldg(&g_srcs[t]);
                    int s1 = __ldg(&g_srcs[t + 1]);
                    uint4 v0 = __ldg(hp + (size_t)s0 * 32 + lane);
                    uint4 v1 = __ldg(hp + (size_t)s1 * 32 + lane);
                    float2 f;
                    f = unpack_h2(v0.x); acc[0] += f.x; acc[1] += f.y;
                    f = unpack_h2(v0.y); acc[2] += f.x; acc[3] += f.y;
                    f = unpack_h2(v0.z); acc[4] += f.x; acc[5] += f.y;
                    f = unpack_h2(v0.w); acc[6] += f.x; acc[7] += f.y;
                    f = unpack_h2(v1.x); acc[0] += f.x; acc[1] += f.y;
                    f = unpack_h2(v1.y); acc[2] += f.x; acc[3] += f.y;
                    f = unpack_h2(v1.z); acc[4] += f.x; acc[5] += f.y;
                    f = unpack_h2(v1.w); acc[6] += f.x; acc[7] += f.y;
                }
                if (t < end) {
                    int s0 = __ldg(&g_srcs[t]);
                    uint4 v0 = __ldg(hp + (size_t)s0 * 32 + lane);
                    float2 f;
                    f = unpack_h2(v0.x); acc[0] += f.x; acc[1] += f.y;
                    f = unpack_h2(v0.y); acc[2] += f.x; acc[3] += f.y;
                    f = unpack_h2(v0.z); acc[4] += f.x; acc[5] += f.y;
                    f = unpack_h2(v0.w); acc[6] += f.x; acc[7] += f.y;
                }
            }
            uint4 o;
            o.x = pack_h2(acc[0], acc[1]);
            o.y = pack_h2(acc[2], acc[3]);
            o.z = pack_h2(acc[4], acc[5]);
            o.w = pack_h2(acc[6], acc[7]);
            *(uint4*)(scr + row * SCR_STR + lane * 4) = o;
        }
    }
    __syncthreads();

    // ---- mainloop: 16 stages x 32 K ----
    float c[2][8][4] = {};
    uint2 ra[2], rb0[2], rb1[2];
#pragma unroll
    for (int j = 0; j < 2; j++) {
        int hoff = j * 16 + aks;
        int kc2 = hoff >> 2;
        ra[j] = *(const uint2*)(scr + am * SCR_STR + (hoff >> 1));
        rb0[j] = __ldg((const uint2*)(Wr + (size_t)am * 128) + kc2);
        rb1[j] = __ldg((const uint2*)(Wr + (size_t)(am + 128) * 128) + kc2);
    }
    for (int st = 0; st < 16; st++) {
        int b = st & 1;
        uint32_t* s0 = bufs + b * 2 * STAGE;
        uint32_t* s1 = s0 + STAGE;
        store_slab(s0, s0 + ASLAB, am, k2, ra[0], rb0[0], rb1[0]);
        store_slab(s1, s1 + ASLAB, am, k2, ra[1], rb0[1], rb1[1]);
        uint2 na[2] = {ra[0], ra[1]}, nb0[2] = {rb0[0], rb0[1]}, nb1[2] = {rb1[0], rb1[1]};
        if (st < 15) {
#pragma unroll
            for (int j = 0; j < 2; j++) {
                int kk = 2 * st + 2 + j;
                int half = kk >> 4;
                int hoff = (kk & 15) * 16 + aks;
                int kc2 = hoff >> 2;
                if (half == 0) {
                    na[j] = *(const uint2*)(scr + am * SCR_STR + (hoff >> 1));
                    nb0[j] = __ldg((const uint2*)(Wr + (size_t)am * 128) + kc2);
                    nb1[j] = __ldg((const uint2*)(Wr + (size_t)(am + 128) * 128) + kc2);
                } else {
                    na[j] = arow ? __ldg((const uint2*)(g_hh + (size_t)gr * 128) + kc2)
                                 : make_uint2(0u, 0u);
                    nb0[j] = __ldg((const uint2*)(Wo + (size_t)am * 128) + kc2);
                    nb1[j] = __ldg((const uint2*)(Wo + (size_t)(am + 128) * 128) + kc2);
                }
            }
        }
        __syncthreads();
        mma_slab(s0, s0 + ASLAB, wm, wn, lane, c);
        mma_slab(s1, s1 + ASLAB, wm, wn, lane, c);
        ra[0] = na[0]; ra[1] = na[1];
        rb0[0] = nb0[0]; rb0[1] = nb0[1];
        rb1[0] = nb1[0]; rb1[1] = nb1[1];
    }

    // ---- epilogue ----
    float ps[8][2], pq[8][2];
#pragma unroll
    for (int nt = 0; nt < 8; nt++)
        ps[nt][0] = ps[nt][1] = pq[nt][0] = pq[nt][1] = 0.f;

#pragma unroll
    for (int mt = 0; mt < 2; mt++) {
        int row = bm + wm * 32 + mt * 16 + lq;
        bool v0 = row < N_NODES, v1 = (row + 8) < N_NODES;
#pragma unroll
        for (int nt = 0; nt < 8; nt++) {
            int col = wn * 64 + nt * 8 + lr * 2;
            float2 bb = __ldg((const float2*)(br + col));
            float o0 = c[mt][nt][0] + bb.x, o1 = c[mt][nt][1] + bb.y;
            float o2 = c[mt][nt][2] + bb.x, o3 = c[mt][nt][3] + bb.y;
            if (v0) {
                g_outh[(size_t)row * 128 + (col >> 1)] = pack_h2(o0, o1);
                ps[nt][0] += o0; pq[nt][0] += o0 * o0;
                ps[nt][1] += o1; pq[nt][1] += o1 * o1;
            }
            if (v1) {
                g_outh[(size_t)(row + 8) * 128 + (col >> 1)] = pack_h2(o2, o3);
                ps[nt][0] += o2; pq[nt][0] += o2 * o2;
                ps[nt][1] += o3; pq[nt][1] += o3 * o3;
            }
        }
    }
#pragma unroll
    for (int nt = 0; nt < 8; nt++)
#pragma unroll
        for (int u = 0; u < 2; u++) {
#pragma unroll
            for (int d = 4; d < 32; d <<= 1) {
                ps[nt][u] += __shfl_xor_sync(0xffffffffu, ps[nt][u], d);
                pq[nt][u] += __shfl_xor_sync(0xffffffffu, pq[nt][u], d);
            }
        }
    if (lq == 0) {
#pragma unroll
        for (int nt = 0; nt < 8; nt++) {
            int col = wn * 64 + nt * 8 + lr * 2;
            atomicAdd(&stats[col], ps[nt][0]);
            atomicAdd(&stats[col + 1], ps[nt][1]);
            atomicAdd(&stats[HID + col], pq[nt][0]);
            atomicAdd(&stats[HID + col + 1], pq[nt][1]);
        }
    }
}

// =================================================================
// UV precompute: U|V = h @ [W1a;W1b]^T ; grid (391, 2), ny: 0=U 1=V
// =================================================================
__global__ void __launch_bounds__(512, 1)
k_gemm_uv() {
    extern __shared__ uint32_t sm[];
    uint32_t* bufs = sm;
    int tid = threadIdx.x;
    int bm = blockIdx.x * 128;
    int ny = blockIdx.y;
    int lane = tid & 31, lq = lane >> 2, lr = lane & 3;
    int wid = tid >> 5, wm = wid & 3, wn = wid >> 2;
    int am = tid >> 2, aks = (tid & 3) * 4;
    int k2 = aks >> 1;
    int gr = bm + am;
    bool arow = gr < N_NODES;
    float c[2][8][4] = {};

    uint2 ra[2], rb0[2], rb1[2];
#pragma unroll
    for (int j = 0; j < 2; j++) {
        int kc2 = (j * 16 + aks) >> 2;
        ra[j] = arow ? __ldg((const uint2*)(g_hh + (size_t)gr * 128) + kc2)
                     : make_uint2(0u, 0u);
        rb0[j] = __ldg((const uint2*)(g_W116 + (size_t)am * 256) + ny * 64 + kc2);
        rb1[j] = __ldg((const uint2*)(g_W116 + (size_t)(am + 128) * 256) + ny * 64 + kc2);
    }
    for (int st = 0; st < 8; st++) {
        int b = st & 1;
        uint32_t* s0 = bufs + b * 2 * STAGE;
        uint32_t* s1 = s0 + STAGE;
        store_slab(s0, s0 + ASLAB, am, k2, ra[0], rb0[0], rb1[0]);
        store_slab(s1, s1 + ASLAB, am, k2, ra[1], rb0[1], rb1[1]);
        uint2 na[2] = {ra[0], ra[1]}, nb0[2] = {rb0[0], rb0[1]}, nb1[2] = {rb1[0], rb1[1]};
        if (st < 7) {
#pragma unroll
            for (int j = 0; j < 2; j++) {
                int kc2 = ((2 * st + 2 + j) * 16 + aks) >> 2;
                na[j] = arow ? __ldg((const uint2*)(g_hh + (size_t)gr * 128) + kc2)
                             : make_uint2(0u, 0u);
                nb0[j] = __ldg((const uint2*)(g_W116 + (size_t)am * 256) + ny * 64 + kc2);
                nb1[j] = __ldg((const uint2*)(g_W116 + (size_t)(am + 128) * 256) + ny * 64 + kc2);
            }
        }
        __syncthreads();
        mma_slab(s0, s0 + ASLAB, wm, wn, lane, c);
        mma_slab(s1, s1 + ASLAB, wm, wn, lane, c);
        ra[0] = na[0]; ra[1] = na[1];
        rb0[0] = nb0[0]; rb0[1] = nb0[1];
        rb1[0] = nb1[0]; rb1[1] = nb1[1];
    }
#pragma unroll
    for (int mt = 0; mt < 2; mt++) {
        int row = bm + wm * 32 + mt * 16 + lq;
#pragma unroll
        for (int nt = 0; nt < 8; nt++) {
            int col = wn * 64 + nt * 8 + lr * 2;
            if (row < N_NODES)
                g_uv[(size_t)row * 256 + ny * 128 + (col >> 1)] =
                    pack_h2(c[mt][nt][0], c[mt][nt][1]);
            if (row + 8 < N_NODES)
                g_uv[(size_t)(row + 8) * 256 + ny * 128 + (col >> 1)] =
                    pack_h2(c[mt][nt][2], c[mt][nt][3]);
        }
    }
}

// =================================================================
// fused edge MLP: z1 = relu(U[src]+V[dst]+b1) assembled in smem,
// then z1 @ W2^T, dot w3, sigmoid.
// =================================================================
__global__ void __launch_bounds__(512, 1)
k_edge_fused(const int* __restrict__ ei, const float* __restrict__ b1,
             const float* __restrict__ b2, const float* __restrict__ W3,
             const float* __restrict__ b3, float* __restrict__ dout) {
    extern __shared__ uint32_t sm[];
    uint32_t* z1sm = sm;                 // 16 slabs x SL
    uint32_t* bufs = sm + Z1U2;          // 4 x BSLAB
    __shared__ float sred[4][128];
    int tid = threadIdx.x;
    int bm = blockIdx.x * 128;
    int lane = tid & 31, lq = lane >> 2, lr = lane & 3;
    int wid = tid >> 5, wm = wid & 3, wn = wid >> 2;
    int am = tid >> 2, aks = (tid & 3) * 4;
    int k2 = aks >> 1;

    // ---- stage 0: assemble z1 in fragment layout ----
    {
        int row = tid >> 2, sub = tid & 3;
        int e = bm + row;
        bool val = e < N_EDGES;
        int nsrc = val ? __ldg(ei + e) : 0;
        int ndst = val ? __ldg(ei + N_EDGES + e) : 0;
        const uint4* up = (const uint4*)(g_uv + (size_t)nsrc * 256);
        const uint4* vp = (const uint4*)(g_uv + (size_t)ndst * 256 + 128);
#pragma unroll
        for (int q = 0; q < 4; q++) {
            int c2b = q * 32 + sub * 8;
            uint4 u0 = __ldg(up + (c2b >> 2));
            uint4 u1 = __ldg(up + (c2b >> 2) + 1);
            uint4 v0 = __ldg(vp + (c2b >> 2));
            uint4 v1 = __ldg(vp + (c2b >> 2) + 1);
            uint32_t uu[8] = {u0.x, u0.y, u0.z, u0.w, u1.x, u1.y, u1.z, u1.w};
            uint32_t vv[8] = {v0.x, v0.y, v0.z, v0.w, v1.x, v1.y, v1.z, v1.w};
            uint32_t* dst = z1sm + (q * 4 + sub) * SL + row;
#pragma unroll
            for (int j = 0; j < 8; j++) {
                int c2 = c2b + j;
                float2 fu = unpack_h2(uu[j]);
                float2 fv = unpack_h2(vv[j]);
                float2 bb = __ldg((const float2*)b1 + c2);
                dst[j * ASTR2] = pack_h2(fmaxf(fu.x + fv.x + bb.x, 0.f),
                                         fmaxf(fu.y + fv.y + bb.y, 0.f));
            }
        }
    }
    __syncthreads();

    // ---- stage 2: z1 @ W2^T (BK=32, B double-buffered) ----
    float c[2][8][4] = {};
    uint2 qb0[2], qb1[2];
#pragma unroll
    for (int j = 0; j < 2; j++) {
        int kc2 = (j * 16 + aks) >> 2;
        qb0[j] = __ldg((const uint2*)(g_W216 + (size_t)am * 128) + kc2);
        qb1[j] = __ldg((const uint2*)(g_W216 + (size_t)(am + 128) * 128) + kc2);
    }
    for (int st = 0; st < 8; st++) {
        int b = st & 1;
        uint32_t* B0 = bufs + b * 2 * BSLAB;
        uint32_t* B1 = B0 + BSLAB;
        store_slab_b(B0, am, k2, qb0[0], qb1[0]);
        store_slab_b(B1, am, k2, qb0[1], qb1[1]);
        uint2 n0[2] = {qb0[0], qb0[1]}, n1[2] = {qb1[0], qb1[1]};
        if (st < 7) {
#pragma unroll
            for (int j = 0; j < 2; j++) {
                int kc2 = ((2 * st + 2 + j) * 16 + aks) >> 2;
                n0[j] = __ldg((const uint2*)(g_W216 + (size_t)am * 128) + kc2);
                n1[j] = __ldg((const uint2*)(g_W216 + (size_t)(am + 128) * 128) + kc2);
            }
        }
        __syncthreads();
        mma_slab(z1sm + (2 * st) * SL, B0, wm, wn, lane, c);
        mma_slab(z1sm + (2 * st + 1) * SL, B1, wm, wn, lane, c);
        qb0[0] = n0[0]; qb0[1] = n0[1];
        qb1[0] = n1[0]; qb1[1] = n1[1];
    }

#pragma unroll
    for (int mt = 0; mt < 2; mt++) {
        float p0 = 0.f, p1 = 0.f;
#pragma unroll
        for (int nt = 0; nt < 8; nt++) {
            int col = wn * 64 + nt * 8 + lr * 2;
            float2 bb = __ldg((const float2*)(b2 + col));
            float2 ww = __ldg((const float2*)(W3 + col));
            p0 = fmaf(fmaxf(c[mt][nt][0] + bb.x, 0.f), ww.x, p0);
            p0 = fmaf(fmaxf(c[mt][nt][1] + bb.y, 0.f), ww.y, p0);
            p1 = fmaf(fmaxf(c[mt][nt][2] + bb.x, 0.f), ww.x, p1);
            p1 = fmaf(fmaxf(c[mt][nt][3] + bb.y, 0.f), ww.y, p1);
        }
        p0 += __shfl_xor_sync(0xffffffffu, p0, 1);
        p0 += __shfl_xor_sync(0xffffffffu, p0, 2);
        p1 += __shfl_xor_sync(0xffffffffu, p1, 1);
        p1 += __shfl_xor_sync(0xffffffffu, p1, 2);
        if (lr == 0) {
            sred[wn][wm * 32 + mt * 16 + lq] = p0;
            sred[wn][wm * 32 + mt * 16 + lq + 8] = p1;
        }
    }
    __syncthreads();
    if (tid < 128) {
        int gr = bm + tid;
        if (gr < N_EDGES) {
            float s = sred[0][tid] + sred[1][tid] + sred[2][tid] + sred[3][tid] + __ldg(b3);
            dout[gr] = 1.f / (1.f + expf(-s));
        }
    }
}

// ---------------------------------------------------------------- launch
extern "C" void kernel_launch(void* const* d_in, const int* in_sizes, int n_in,
                              void* d_out, int out_size) {
    const float* x     = (const float*)d_in[0];
    const int*   ei    = (const int*)  d_in[1];
    const float* Win   = (const float*)d_in[2];
    const float* Wrel  = (const float*)d_in[3];
    const float* brel  = (const float*)d_in[4];
    const float* Wroot = (const float*)d_in[5];
    const float* gamma = (const float*)d_in[6];
    const float* beta  = (const float*)d_in[7];
    const float* W1    = (const float*)d_in[8];
    const float* b1    = (const float*)d_in[9];
    const float* W2    = (const float*)d_in[10];
    const float* b2    = (const float*)d_in[11];
    const float* W3    = (const float*)d_in[12];
    const float* b3    = (const float*)d_in[13];
    float* out = (float*)d_out;

    cudaFuncSetAttribute(k_gemm_node, cudaFuncAttributeMaxDynamicSharedMemorySize, NSMEM);
    cudaFuncSetAttribute(k_gemm_uv,   cudaFuncAttributeMaxDynamicSharedMemorySize, UVSMEM);
    cudaFuncSetAttribute(k_edge_fused, cudaFuncAttributeMaxDynamicSharedMemorySize, ESMEM);

    int ncvt = LAYERS * 256 * 128 + 256 * 256 + 256 * 128;
    k_cvt_weights<<<(ncvt + 255) / 256, 256>>>(Wrel, Wroot, W1, W2);
    k_input_fc<<<(N_NODES * 128 + 255) / 256, 256>>>(x, Win);
    k_csr_count<<<(N_EDGES + 255) / 256, 256>>>(ei);
    int nblk = (N_NODES + 1023) / 1024;   // 49
    k_scan1<<<nblk, 1024>>>();
    k_scan2<<<1, 32>>>(nblk);
    k_scan3<<<(N_NODES + 255) / 256, 256>>>();
    k_csr_fill<<<(N_EDGES + 255) / 256, 256>>>(ei);

    int node_grid = (N_NODES + 127) / 128;     // 391
    for (int l = 0; l < LAYERS; l++) {
        k_gemm_node<<<node_grid, 512, NSMEM>>>(l, brel + (size_t)l * HID);
        k_bn_apply<<<(N_NODES * 128 + 255) / 256, 256>>>(
            l, gamma + (size_t)l * HID, beta + (size_t)l * HID);
    }

    dim3 uv_grid(node_grid, 2);
    k_gemm_uv<<<uv_grid, 512, UVSMEM>>>();
    int edge_grid = (N_EDGES + 127) / 128;     // 3907
    k_edge_fused<<<edge_grid, 512, ESMEM>>>(ei, b1, b2, W3, b3, out);
}

// round 14
// speedup vs baseline: 1.4951x; 1.0381x over previous
#include <cuda_runtime.h>
#include <cuda_fp16.h>
#include <cstdint>
#include <math.h>

#define N_NODES 50000
#define N_EDGES 500000
#define HID 256
#define LAYERS 15

// ---------------------------------------------------------------- scratch
__device__ float    g_h   [(size_t)N_NODES * HID];    // fp32 residual carry
__device__ uint32_t g_hh  [(size_t)N_NODES * 128];    // h as half2
__device__ uint32_t g_outh[(size_t)N_NODES * 128];    // pre-BN out as half2
__device__ uint32_t g_uv  [(size_t)N_NODES * 256];    // U|V per node (half2)
__device__ float    g_statsf[LAYERS * 512];           // per-layer BN sum/sumsq
// fp16 weights
__device__ uint32_t g_Wrel16 [LAYERS * 256 * 128];
__device__ uint32_t g_Wroot16[LAYERS * 256 * 128];
__device__ uint32_t g_W116[256 * 256];
__device__ uint32_t g_W216[256 * 128];
// CSR
__device__ int g_deg[N_NODES];
__device__ int g_off[N_NODES + 1];
__device__ int g_pos[N_NODES];
__device__ int g_srcs[N_EDGES];
__device__ int g_bsum[64];
__device__ int g_bsum2[64];

// ---------------------------------------------------------------- helpers
__device__ __forceinline__ uint32_t pack_h2(float x, float y) {
    __half2 h = __float22half2_rn(make_float2(x, y));
    return *(uint32_t*)&h;
}
__device__ __forceinline__ float2 unpack_h2(uint32_t u) {
    return __half22float2(*(__half2*)&u);
}
__device__ __forceinline__ void mma16(float* c, uint32_t a0, uint32_t a1,
                                      uint32_t a2, uint32_t a3,
                                      uint32_t b0, uint32_t b1) {
    asm volatile(
        "mma.sync.aligned.m16n8k16.row.col.f32.f16.f16.f32 "
        "{%0,%1,%2,%3}, {%4,%5,%6,%7}, {%8,%9}, {%0,%1,%2,%3};"
        : "+f"(c[0]), "+f"(c[1]), "+f"(c[2]), "+f"(c[3])
        : "r"(a0), "r"(a1), "r"(a2), "r"(a3), "r"(b0), "r"(b1));
}
__device__ __forceinline__ void acc_row(float* acc, uint4 v) {
    float2 f;
    f = unpack_h2(v.x); acc[0] += f.x; acc[1] += f.y;
    f = unpack_h2(v.y); acc[2] += f.x; acc[3] += f.y;
    f = unpack_h2(v.z); acc[4] += f.x; acc[5] += f.y;
    f = unpack_h2(v.w); acc[6] += f.x; acc[7] += f.y;
}

// smem (half2 units):  A2[k2 8][row 128]  B2[k2 8][col 256], strides ≡ 8 mod 32
#define ASTR2 136
#define BSTR2 264
#define ASLAB (8 * ASTR2)              // 1088
#define BSLAB (8 * BSTR2)              // 2112
#define STAGE (ASLAB + BSLAB)          // 3200 uints (one 16-K slab A+B)
#define SCR_STR 132                    // gather scratch row stride (uint32)
#define NSMEM ((4 * STAGE + 128 * SCR_STR) * 4)   // 118784 B
#define UVSMEM (4 * STAGE * 4)         // 51200 B
#define SL 1096                        // z1 slab stride (padded: conflict-free fill)
#define Z1U2 (16 * SL)                 // 17536
#define ESMEM ((Z1U2 + 4 * BSLAB) * 4) // 103936 B

__device__ __forceinline__ void store_slab(uint32_t* As, uint32_t* Bs, int am, int k2,
                                           uint2 ra, uint2 rb0, uint2 rb1) {
    As[(k2 + 0) * ASTR2 + am] = ra.x;
    As[(k2 + 1) * ASTR2 + am] = ra.y;
    Bs[(k2 + 0) * BSTR2 + am] = rb0.x;
    Bs[(k2 + 1) * BSTR2 + am] = rb0.y;
    Bs[(k2 + 0) * BSTR2 + am + 128] = rb1.x;
    Bs[(k2 + 1) * BSTR2 + am + 128] = rb1.y;
}
__device__ __forceinline__ void store_slab_b(uint32_t* Bs, int am, int k2,
                                             uint2 rb0, uint2 rb1) {
    Bs[(k2 + 0) * BSTR2 + am] = rb0.x;
    Bs[(k2 + 1) * BSTR2 + am] = rb0.y;
    Bs[(k2 + 0) * BSTR2 + am + 128] = rb1.x;
    Bs[(k2 + 1) * BSTR2 + am + 128] = rb1.y;
}

__device__ __forceinline__ void mma_slab(const uint32_t* As, const uint32_t* Bs,
                                         int wm, int wn, int lane,
                                         float c[2][8][4]) {
    int g = lane >> 2, t = lane & 3;
    uint32_t b0[8], b1[8];
#pragma unroll
    for (int nt = 0; nt < 8; nt++) {
        int C = wn * 64 + nt * 8 + g;
        b0[nt] = Bs[t * BSTR2 + C];
        b1[nt] = Bs[(t + 4) * BSTR2 + C];
    }
#pragma unroll
    for (int mt = 0; mt < 2; mt++) {
        int R = wm * 32 + mt * 16 + g;
        uint32_t a0 = As[t * ASTR2 + R];
        uint32_t a1 = As[t * ASTR2 + R + 8];
        uint32_t a2 = As[(t + 4) * ASTR2 + R];
        uint32_t a3 = As[(t + 4) * ASTR2 + R + 8];
#pragma unroll
        for (int nt = 0; nt < 8; nt++)
            mma16(c[mt][nt], a0, a1, a2, a3, b0[nt], b1[nt]);
    }
}

// ---------------------------------------------------------------- small kernels
__global__ void k_cvt_weights(const float* __restrict__ Wrel,
                              const float* __restrict__ Wroot,
                              const float* __restrict__ W1,
                              const float* __restrict__ W2) {
    const int NREL = LAYERS * 256 * 128;
    const int NW1 = 256 * 256;
    const int NW2 = 256 * 128;
    int i = blockIdx.x * blockDim.x + threadIdx.x;
    if (i < LAYERS * 512) g_statsf[i] = 0.f;
    if (i < NREL) {
        g_Wrel16[i] = pack_h2(Wrel[2 * i], Wrel[2 * i + 1]);
        g_Wroot16[i] = pack_h2(Wroot[2 * i], Wroot[2 * i + 1]);
    } else {
        int j = i - NREL;
        if (j < NW1) g_W116[j] = pack_h2(W1[2 * j], W1[2 * j + 1]);
        else if (j - NW1 < NW2) {
            int k = j - NW1;
            g_W216[k] = pack_h2(W2[2 * k], W2[2 * k + 1]);
        }
    }
}

__global__ void k_input_fc(const float* __restrict__ x, const float* __restrict__ Win) {
    int idx = blockIdx.x * blockDim.x + threadIdx.x;   // half2 units
    if (idx < N_NODES) g_deg[idx] = 0;
    if (idx >= N_NODES * 128) return;
    int node = idx >> 7, c0 = (idx & 127) * 2;
    float x0 = x[node * 2], x1 = x[node * 2 + 1];
    float h0 = x0 * Win[c0 * 2] + x1 * Win[c0 * 2 + 1];
    float h1 = x0 * Win[c0 * 2 + 2] + x1 * Win[c0 * 2 + 3];
    ((float2*)g_h)[idx] = make_float2(h0, h1);
    g_hh[idx] = pack_h2(h0, h1);
}

__global__ void k_csr_count(const int* __restrict__ ei) {
    int e = blockIdx.x * blockDim.x + threadIdx.x;
    if (e >= N_EDGES) return;
    atomicAdd(&g_deg[__ldg(ei + N_EDGES + e)], 1);
}

// multi-block scan: block-local exclusive + block sums
__global__ void k_scan1() {
    __shared__ int wsum[32];
    int tid = threadIdx.x, lane = tid & 31, wid = tid >> 5;
    int i = blockIdx.x * 1024 + tid;
    int v = (i < N_NODES) ? g_deg[i] : 0;
    int x = v;
#pragma unroll
    for (int d = 1; d < 32; d <<= 1) {
        int y = __shfl_up_sync(0xffffffffu, x, d);
        if (lane >= d) x += y;
    }
    if (lane == 31) wsum[wid] = x;
    __syncthreads();
    if (wid == 0) {
        int w = wsum[lane];
#pragma unroll
        for (int d = 1; d < 32; d <<= 1) {
            int y = __shfl_up_sync(0xffffffffu, w, d);
            if (lane >= d) w += y;
        }
        wsum[lane] = w;
    }
    __syncthreads();
    int incl = x + (wid > 0 ? wsum[wid - 1] : 0);
    if (i < N_NODES) g_off[i] = incl - v;       // block-local exclusive
    if (tid == 0) g_bsum[blockIdx.x] = wsum[31];
}

__global__ void k_scan2(int nblk) {
    if (threadIdx.x == 0) {
        int acc = 0;
        for (int b = 0; b < nblk; b++) { g_bsum2[b] = acc; acc += g_bsum[b]; }
        g_off[N_NODES] = acc;
    }
}

__global__ void k_scan3() {
    int i = blockIdx.x * blockDim.x + threadIdx.x;
    if (i >= N_NODES) return;
    int o = g_off[i] + g_bsum2[i >> 10];
    g_off[i] = o;
    g_pos[i] = o;
}

__global__ void k_csr_fill(const int* __restrict__ ei) {
    int e = blockIdx.x * blockDim.x + threadIdx.x;
    if (e >= N_EDGES) return;
    int d = __ldg(ei + N_EDGES + e);
    int p = atomicAdd(&g_pos[d], 1);
    g_srcs[p] = __ldg(ei + e);
}

// ---- BN finalize + apply fused ----
__global__ void k_bn_apply(int layer, const float* __restrict__ gm,
                           const float* __restrict__ bt) {
    __shared__ float ssc[HID], ssh[HID];
    const float* stats = g_statsf + (size_t)layer * 512;
    int tid = threadIdx.x;
    if (tid < HID) {
        float mean = stats[tid] * (1.f / N_NODES);
        float var  = stats[HID + tid] * (1.f / N_NODES) - mean * mean;
        float rstd = rsqrtf(var + 1e-5f);
        float sc = rstd * __ldg(gm + tid);
        ssc[tid] = sc;
        ssh[tid] = __ldg(bt + tid) - mean * sc;
    }
    __syncthreads();
    int idx = blockIdx.x * blockDim.x + tid;
    if (idx >= N_NODES * 128) return;
    int c0 = (idx & 127) * 2;
    float2 o = unpack_h2(g_outh[idx]);
    float2 hv = ((float2*)g_h)[idx];
    hv.x += fmaxf(fmaf(o.x, ssc[c0], ssh[c0]), 0.f);
    hv.y += fmaxf(fmaf(o.y, ssc[c0 + 1], ssh[c0 + 1]), 0.f);
    ((float2*)g_h)[idx] = hv;
    g_hh[idx] = pack_h2(hv.x, hv.y);
}

// =================================================================
// node layer: phase 0 gathers agg into smem (edge loop unrolled x4),
// BK=32 fp16 GEMM, fused BN stats epilogue.
// =================================================================
__global__ void __launch_bounds__(512, 1)
k_gemm_node(int layer, const float* __restrict__ br) {
    extern __shared__ uint32_t sm[];
    uint32_t* bufs = sm;
    uint32_t* scr  = sm + 4 * STAGE;
    int tid = threadIdx.x;
    int bm = blockIdx.x * 128;
    int lane = tid & 31, lq = lane >> 2, lr = lane & 3;
    int wid = tid >> 5, wm = wid & 3, wn = wid >> 2;
    int am = tid >> 2, aks = (tid & 3) * 4;
    int k2 = aks >> 1;
    int gr = bm + am;
    bool arow = gr < N_NODES;
    const uint32_t* Wr = g_Wrel16 + (size_t)layer * 256 * 128;
    const uint32_t* Wo = g_Wroot16 + (size_t)layer * 256 * 128;
    float* stats = g_statsf + (size_t)layer * 512;

    // ---- phase 0: gather (unroll x4, dual accumulator banks) ----
    {
        const uint4* hp = (const uint4*)g_hh;
        for (int i = 0; i < 8; i++) {
            int row = wid * 8 + i;
            int node = bm + row;
            float acc[8] = {};
            float acc2[8] = {};
            if (node < N_NODES) {
                int beg = g_off[node], end = g_off[node + 1];
                int t = beg;
                for (; t + 3 < end; t += 4) {
                    int s0 = __ldg(&g_srcs[t]);
                    int s1 = __ldg(&g_srcs[t + 1]);
                    int s2 = __ldg(&g_srcs[t + 2]);
                    int s3 = __ldg(&g_srcs[t + 3]);
                    uint4 v0 = __ldg(hp + (size_t)s0 * 32 + lane);
                    uint4 v1 = __ldg(hp + (size_t)s1 * 32 + lane);
                    uint4 v2 = __ldg(hp + (size_t)s2 * 32 + lane);
                    uint4 v3 = __ldg(hp + (size_t)s3 * 32 + lane);
                    acc_row(acc, v0);
                    acc_row(acc2, v1);
                    acc_row(acc, v2);
                    acc_row(acc2, v3);
                }
                for (; t < end; t++) {
                    int s0 = __ldg(&g_srcs[t]);
                    uint4 v0 = __ldg(hp + (size_t)s0 * 32 + lane);
                    acc_row(acc, v0);
                }
            }
#pragma unroll
            for (int u = 0; u < 8; u++) acc[u] += acc2[u];
            uint4 o;
            o.x = pack_h2(acc[0], acc[1]);
            o.y = pack_h2(acc[2], acc[3]);
            o.z = pack_h2(acc[4], acc[5]);
            o.w = pack_h2(acc[6], acc[7]);
            *(uint4*)(scr + row * SCR_STR + lane * 4) = o;
        }
    }
    __syncthreads();

    // ---- mainloop: 16 stages x 32 K ----
    float c[2][8][4] = {};
    uint2 ra[2], rb0[2], rb1[2];
#pragma unroll
    for (int j = 0; j < 2; j++) {
        int hoff = j * 16 + aks;
        int kc2 = hoff >> 2;
        ra[j] = *(const uint2*)(scr + am * SCR_STR + (hoff >> 1));
        rb0[j] = __ldg((const uint2*)(Wr + (size_t)am * 128) + kc2);
        rb1[j] = __ldg((const uint2*)(Wr + (size_t)(am + 128) * 128) + kc2);
    }
    for (int st = 0; st < 16; st++) {
        int b = st & 1;
        uint32_t* s0 = bufs + b * 2 * STAGE;
        uint32_t* s1 = s0 + STAGE;
        store_slab(s0, s0 + ASLAB, am, k2, ra[0], rb0[0], rb1[0]);
        store_slab(s1, s1 + ASLAB, am, k2, ra[1], rb0[1], rb1[1]);
        uint2 na[2] = {ra[0], ra[1]}, nb0[2] = {rb0[0], rb0[1]}, nb1[2] = {rb1[0], rb1[1]};
        if (st < 15) {
#pragma unroll
            for (int j = 0; j < 2; j++) {
                int kk = 2 * st + 2 + j;
                int half = kk >> 4;
                int hoff = (kk & 15) * 16 + aks;
                int kc2 = hoff >> 2;
                if (half == 0) {
                    na[j] = *(const uint2*)(scr + am * SCR_STR + (hoff >> 1));
                    nb0[j] = __ldg((const uint2*)(Wr + (size_t)am * 128) + kc2);
                    nb1[j] = __ldg((const uint2*)(Wr + (size_t)(am + 128) * 128) + kc2);
                } else {
                    na[j] = arow ? __ldg((const uint2*)(g_hh + (size_t)gr * 128) + kc2)
                                 : make_uint2(0u, 0u);
                    nb0[j] = __ldg((const uint2*)(Wo + (size_t)am * 128) + kc2);
                    nb1[j] = __ldg((const uint2*)(Wo + (size_t)(am + 128) * 128) + kc2);
                }
            }
        }
        __syncthreads();
        mma_slab(s0, s0 + ASLAB, wm, wn, lane, c);
        mma_slab(s1, s1 + ASLAB, wm, wn, lane, c);
        ra[0] = na[0]; ra[1] = na[1];
        rb0[0] = nb0[0]; rb0[1] = nb0[1];
        rb1[0] = nb1[0]; rb1[1] = nb1[1];
    }

    // ---- epilogue ----
    float ps[8][2], pq[8][2];
#pragma unroll
    for (int nt = 0; nt < 8; nt++)
        ps[nt][0] = ps[nt][1] = pq[nt][0] = pq[nt][1] = 0.f;

#pragma unroll
    for (int mt = 0; mt < 2; mt++) {
        int row = bm + wm * 32 + mt * 16 + lq;
        bool v0 = row < N_NODES, v1 = (row + 8) < N_NODES;
#pragma unroll
        for (int nt = 0; nt < 8; nt++) {
            int col = wn * 64 + nt * 8 + lr * 2;
            float2 bb = __ldg((const float2*)(br + col));
            float o0 = c[mt][nt][0] + bb.x, o1 = c[mt][nt][1] + bb.y;
            float o2 = c[mt][nt][2] + bb.x, o3 = c[mt][nt][3] + bb.y;
            if (v0) {
                g_outh[(size_t)row * 128 + (col >> 1)] = pack_h2(o0, o1);
                ps[nt][0] += o0; pq[nt][0] += o0 * o0;
                ps[nt][1] += o1; pq[nt][1] += o1 * o1;
            }
            if (v1) {
                g_outh[(size_t)(row + 8) * 128 + (col >> 1)] = pack_h2(o2, o3);
                ps[nt][0] += o2; pq[nt][0] += o2 * o2;
                ps[nt][1] += o3; pq[nt][1] += o3 * o3;
            }
        }
    }
#pragma unroll
    for (int nt = 0; nt < 8; nt++)
#pragma unroll
        for (int u = 0; u < 2; u++) {
#pragma unroll
            for (int d = 4; d < 32; d <<= 1) {
                ps[nt][u] += __shfl_xor_sync(0xffffffffu, ps[nt][u], d);
                pq[nt][u] += __shfl_xor_sync(0xffffffffu, pq[nt][u], d);
            }
        }
    if (lq == 0) {
#pragma unroll
        for (int nt = 0; nt < 8; nt++) {
            int col = wn * 64 + nt * 8 + lr * 2;
            atomicAdd(&stats[col], ps[nt][0]);
            atomicAdd(&stats[col + 1], ps[nt][1]);
            atomicAdd(&stats[HID + col], pq[nt][0]);
            atomicAdd(&stats[HID + col + 1], pq[nt][1]);
        }
    }
}

// =================================================================
// UV precompute: U|V = h @ [W1a;W1b]^T ; grid (391, 2), ny: 0=U 1=V
// =================================================================
__global__ void __launch_bounds__(512, 1)
k_gemm_uv() {
    extern __shared__ uint32_t sm[];
    uint32_t* bufs = sm;
    int tid = threadIdx.x;
    int bm = blockIdx.x * 128;
    int ny = blockIdx.y;
    int lane = tid & 31, lq = lane >> 2, lr = lane & 3;
    int wid = tid >> 5, wm = wid & 3, wn = wid >> 2;
    int am = tid >> 2, aks = (tid & 3) * 4;
    int k2 = aks >> 1;
    int gr = bm + am;
    bool arow = gr < N_NODES;
    float c[2][8][4] = {};

    uint2 ra[2], rb0[2], rb1[2];
#pragma unroll
    for (int j = 0; j < 2; j++) {
        int kc2 = (j * 16 + aks) >> 2;
        ra[j] = arow ? __ldg((const uint2*)(g_hh + (size_t)gr * 128) + kc2)
                     : make_uint2(0u, 0u);
        rb0[j] = __ldg((const uint2*)(g_W116 + (size_t)am * 256) + ny * 64 + kc2);
        rb1[j] = __ldg((const uint2*)(g_W116 + (size_t)(am + 128) * 256) + ny * 64 + kc2);
    }
    for (int st = 0; st < 8; st++) {
        int b = st & 1;
        uint32_t* s0 = bufs + b * 2 * STAGE;
        uint32_t* s1 = s0 + STAGE;
        store_slab(s0, s0 + ASLAB, am, k2, ra[0], rb0[0], rb1[0]);
        store_slab(s1, s1 + ASLAB, am, k2, ra[1], rb0[1], rb1[1]);
        uint2 na[2] = {ra[0], ra[1]}, nb0[2] = {rb0[0], rb0[1]}, nb1[2] = {rb1[0], rb1[1]};
        if (st < 7) {
#pragma unroll
            for (int j = 0; j < 2; j++) {
                int kc2 = ((2 * st + 2 + j) * 16 + aks) >> 2;
                na[j] = arow ? __ldg((const uint2*)(g_hh + (size_t)gr * 128) + kc2)
                             : make_uint2(0u, 0u);
                nb0[j] = __ldg((const uint2*)(g_W116 + (size_t)am * 256) + ny * 64 + kc2);
                nb1[j] = __ldg((const uint2*)(g_W116 + (size_t)(am + 128) * 256) + ny * 64 + kc2);
            }
        }
        __syncthreads();
        mma_slab(s0, s0 + ASLAB, wm, wn, lane, c);
        mma_slab(s1, s1 + ASLAB, wm, wn, lane, c);
        ra[0] = na[0]; ra[1] = na[1];
        rb0[0] = nb0[0]; rb0[1] = nb0[1];
        rb1[0] = nb1[0]; rb1[1] = nb1[1];
    }
#pragma unroll
    for (int mt = 0; mt < 2; mt++) {
        int row = bm + wm * 32 + mt * 16 + lq;
#pragma unroll
        for (int nt = 0; nt < 8; nt++) {
            int col = wn * 64 + nt * 8 + lr * 2;
            if (row < N_NODES)
                g_uv[(size_t)row * 256 + ny * 128 + (col >> 1)] =
                    pack_h2(c[mt][nt][0], c[mt][nt][1]);
            if (row + 8 < N_NODES)
                g_uv[(size_t)(row + 8) * 256 + ny * 128 + (col >> 1)] =
                    pack_h2(c[mt][nt][2], c[mt][nt][3]);
        }
    }
}

// =================================================================
// fused edge MLP: z1 = relu(U[src]+V[dst]+b1) assembled in smem,
// then z1 @ W2^T, dot w3, sigmoid.
// =================================================================
__global__ void __launch_bounds__(512, 1)
k_edge_fused(const int* __restrict__ ei, const float* __restrict__ b1,
             const float* __restrict__ b2, const float* __restrict__ W3,
             const float* __restrict__ b3, float* __restrict__ dout) {
    extern __shared__ uint32_t sm[];
    uint32_t* z1sm = sm;                 // 16 slabs x SL
    uint32_t* bufs = sm + Z1U2;          // 4 x BSLAB
    __shared__ float sred[4][128];
    int tid = threadIdx.x;
    int bm = blockIdx.x * 128;
    int lane = tid & 31, lq = lane >> 2, lr = lane & 3;
    int wid = tid >> 5, wm = wid & 3, wn = wid >> 2;
    int am = tid >> 2, aks = (tid & 3) * 4;
    int k2 = aks >> 1;

    // ---- stage 0: assemble z1 in fragment layout ----
    {
        int row = tid >> 2, sub = tid & 3;
        int e = bm + row;
        bool val = e < N_EDGES;
        int nsrc = val ? __ldg(ei + e) : 0;
        int ndst = val ? __ldg(ei + N_EDGES + e) : 0;
        const uint4* up = (const uint4*)(g_uv + (size_t)nsrc * 256);
        const uint4* vp = (const uint4*)(g_uv + (size_t)ndst * 256 + 128);
#pragma unroll
        for (int q = 0; q < 4; q++) {
            int c2b = q * 32 + sub * 8;
            uint4 u0 = __ldg(up + (c2b >> 2));
            uint4 u1 = __ldg(up + (c2b >> 2) + 1);
            uint4 v0 = __ldg(vp + (c2b >> 2));
            uint4 v1 = __ldg(vp + (c2b >> 2) + 1);
            uint32_t uu[8] = {u0.x, u0.y, u0.z, u0.w, u1.x, u1.y, u1.z, u1.w};
            uint32_t vv[8] = {v0.x, v0.y, v0.z, v0.w, v1.x, v1.y, v1.z, v1.w};
            uint32_t* dst = z1sm + (q * 4 + sub) * SL + row;
#pragma unroll
            for (int j = 0; j < 8; j++) {
                int c2 = c2b + j;
                float2 fu = unpack_h2(uu[j]);
                float2 fv = unpack_h2(vv[j]);
                float2 bb = __ldg((const float2*)b1 + c2);
                dst[j * ASTR2] = pack_h2(fmaxf(fu.x + fv.x + bb.x, 0.f),
                                         fmaxf(fu.y + fv.y + bb.y, 0.f));
            }
        }
    }
    __syncthreads();

    // ---- stage 2: z1 @ W2^T (BK=32, B double-buffered) ----
    float c[2][8][4] = {};
    uint2 qb0[2], qb1[2];
#pragma unroll
    for (int j = 0; j < 2; j++) {
        int kc2 = (j * 16 + aks) >> 2;
        qb0[j] = __ldg((const uint2*)(g_W216 + (size_t)am * 128) + kc2);
        qb1[j] = __ldg((const uint2*)(g_W216 + (size_t)(am + 128) * 128) + kc2);
    }
    for (int st = 0; st < 8; st++) {
        int b = st & 1;
        uint32_t* B0 = bufs + b * 2 * BSLAB;
        uint32_t* B1 = B0 + BSLAB;
        store_slab_b(B0, am, k2, qb0[0], qb1[0]);
        store_slab_b(B1, am, k2, qb0[1], qb1[1]);
        uint2 n0[2] = {qb0[0], qb0[1]}, n1[2] = {qb1[0], qb1[1]};
        if (st < 7) {
#pragma unroll
            for (int j = 0; j < 2; j++) {
                int kc2 = ((2 * st + 2 + j) * 16 + aks) >> 2;
                n0[j] = __ldg((const uint2*)(g_W216 + (size_t)am * 128) + kc2);
                n1[j] = __ldg((const uint2*)(g_W216 + (size_t)(am + 128) * 128) + kc2);
            }
        }
        __syncthreads();
        mma_slab(z1sm + (2 * st) * SL, B0, wm, wn, lane, c);
        mma_slab(z1sm + (2 * st + 1) * SL, B1, wm, wn, lane, c);
        qb0[0] = n0[0]; qb0[1] = n0[1];
        qb1[0] = n1[0]; qb1[1] = n1[1];
    }

#pragma unroll
    for (int mt = 0; mt < 2; mt++) {
        float p0 = 0.f, p1 = 0.f;
#pragma unroll
        for (int nt = 0; nt < 8; nt++) {
            int col = wn * 64 + nt * 8 + lr * 2;
            float2 bb = __ldg((const float2*)(b2 + col));
            float2 ww = __ldg((const float2*)(W3 + col));
            p0 = fmaf(fmaxf(c[mt][nt][0] + bb.x, 0.f), ww.x, p0);
            p0 = fmaf(fmaxf(c[mt][nt][1] + bb.y, 0.f), ww.y, p0);
            p1 = fmaf(fmaxf(c[mt][nt][2] + bb.x, 0.f), ww.x, p1);
            p1 = fmaf(fmaxf(c[mt][nt][3] + bb.y, 0.f), ww.y, p1);
        }
        p0 += __shfl_xor_sync(0xffffffffu, p0, 1);
        p0 += __shfl_xor_sync(0xffffffffu, p0, 2);
        p1 += __shfl_xor_sync(0xffffffffu, p1, 1);
        p1 += __shfl_xor_sync(0xffffffffu, p1, 2);
        if (lr == 0) {
            sred[wn][wm * 32 + mt * 16 + lq] = p0;
            sred[wn][wm * 32 + mt * 16 + lq + 8] = p1;
        }
    }
    __syncthreads();
    if (tid < 128) {
        int gr = bm + tid;
        if (gr < N_EDGES) {
            float s = sred[0][tid] + sred[1][tid] + sred[2][tid] + sred[3][tid] + __ldg(b3);
            dout[gr] = 1.f / (1.f + expf(-s));
        }
    }
}

// ---------------------------------------------------------------- launch
extern "C" void kernel_launch(void* const* d_in, const int* in_sizes, int n_in,
                              void* d_out, int out_size) {
    const float* x     = (const float*)d_in[0];
    const int*   ei    = (const int*)  d_in[1];
    const float* Win   = (const float*)d_in[2];
    const float* Wrel  = (const float*)d_in[3];
    const float* brel  = (const float*)d_in[4];
    const float* Wroot = (const float*)d_in[5];
    const float* gamma = (const float*)d_in[6];
    const float* beta  = (const float*)d_in[7];
    const float* W1    = (const float*)d_in[8];
    const float* b1    = (const float*)d_in[9];
    const float* W2    = (const float*)d_in[10];
    const float* b2    = (const float*)d_in[11];
    const float* W3    = (const float*)d_in[12];
    const float* b3    = (const float*)d_in[13];
    float* out = (float*)d_out;

    cudaFuncSetAttribute(k_gemm_node, cudaFuncAttributeMaxDynamicSharedMemorySize, NSMEM);
    cudaFuncSetAttribute(k_gemm_uv,   cudaFuncAttributeMaxDynamicSharedMemorySize, UVSMEM);
    cudaFuncSetAttribute(k_edge_fused, cudaFuncAttributeMaxDynamicSharedMemorySize, ESMEM);

    int ncvt = LAYERS * 256 * 128 + 256 * 256 + 256 * 128;
    k_cvt_weights<<<(ncvt + 255) / 256, 256>>>(Wrel, Wroot, W1, W2);
    k_input_fc<<<(N_NODES * 128 + 255) / 256, 256>>>(x, Win);
    k_csr_count<<<(N_EDGES + 255) / 256, 256>>>(ei);
    int nblk = (N_NODES + 1023) / 1024;   // 49
    k_scan1<<<nblk, 1024>>>();
    k_scan2<<<1, 32>>>(nblk);
    k_scan3<<<(N_NODES + 255) / 256, 256>>>();
    k_csr_fill<<<(N_EDGES + 255) / 256, 256>>>(ei);

    int node_grid = (N_NODES + 127) / 128;     // 391
    for (int l = 0; l < LAYERS; l++) {
        k_gemm_node<<<node_grid, 512, NSMEM>>>(l, brel + (size_t)l * HID);
        k_bn_apply<<<(N_NODES * 128 + 255) / 256, 256>>>(
            l, gamma + (size_t)l * HID, beta + (size_t)l * HID);
    }

    dim3 uv_grid(node_grid, 2);
    k_gemm_uv<<<uv_grid, 512, UVSMEM>>>();
    int edge_grid = (N_EDGES + 127) / 128;     // 3907
    k_edge_fused<<<edge_grid, 512, ESMEM>>>(ei, b1, b2, W3, b3, out);
}

// round 15
// speedup vs baseline: 1.5590x; 1.0427x over previous
#include <cuda_runtime.h>
#include <cuda_fp16.h>
#include <cstdint>
#include <math.h>

#define N_NODES 50000
#define N_EDGES 500000
#define HID 256
#define LAYERS 15

// ---------------------------------------------------------------- scratch
__device__ float    g_h   [(size_t)N_NODES * HID];    // fp32 residual carry
__device__ uint32_t g_hh  [(size_t)N_NODES * 128];    // h as half2
__device__ uint32_t g_outh[(size_t)N_NODES * 128];    // pre-BN out as half2
__device__ uint32_t g_uv  [(size_t)N_NODES * 256];    // U|V per node (half2)
__device__ float    g_statsf[LAYERS * 512];           // per-layer BN sum/sumsq
// fp16 weights
__device__ uint32_t g_Wrel16 [LAYERS * 256 * 128];
__device__ uint32_t g_Wroot16[LAYERS * 256 * 128];
__device__ uint32_t g_W116[256 * 256];
__device__ uint32_t g_W216[256 * 128];
// CSR
__device__ int g_deg[N_NODES];
__device__ int g_off[N_NODES + 1];
__device__ int g_pos[N_NODES];
__device__ int g_srcs[N_EDGES];
__device__ int g_bsum[64];
__device__ int g_bsum2[64];

// ---------------------------------------------------------------- helpers
__device__ __forceinline__ uint32_t pack_h2(float x, float y) {
    __half2 h = __float22half2_rn(make_float2(x, y));
    return *(uint32_t*)&h;
}
__device__ __forceinline__ float2 unpack_h2(uint32_t u) {
    return __half22float2(*(__half2*)&u);
}
__device__ __forceinline__ uint32_t hadd2u(uint32_t a, uint32_t b) {
    __half2 r = __hadd2(*(__half2*)&a, *(__half2*)&b);
    return *(uint32_t*)&r;
}
__device__ __forceinline__ void mma16(float* c, uint32_t a0, uint32_t a1,
                                      uint32_t a2, uint32_t a3,
                                      uint32_t b0, uint32_t b1) {
    asm volatile(
        "mma.sync.aligned.m16n8k16.row.col.f32.f16.f16.f32 "
        "{%0,%1,%2,%3}, {%4,%5,%6,%7}, {%8,%9}, {%0,%1,%2,%3};"
        : "+f"(c[0]), "+f"(c[1]), "+f"(c[2]), "+f"(c[3])
        : "r"(a0), "r"(a1), "r"(a2), "r"(a3), "r"(b0), "r"(b1));
}
__device__ __forceinline__ void acc_row(float* acc, uint4 v) {
    float2 f;
    f = unpack_h2(v.x); acc[0] += f.x; acc[1] += f.y;
    f = unpack_h2(v.y); acc[2] += f.x; acc[3] += f.y;
    f = unpack_h2(v.z); acc[4] += f.x; acc[5] += f.y;
    f = unpack_h2(v.w); acc[6] += f.x; acc[7] += f.y;
}

// smem (half2 units):  A2[k2 8][row 128]  B2[k2 8][col 256], strides ≡ 8 mod 32
#define ASTR2 136
#define BSTR2 264
#define ASLAB (8 * ASTR2)              // 1088
#define BSLAB (8 * BSTR2)              // 2112
#define STAGE (ASLAB + BSLAB)          // 3200 uints (one 16-K slab A+B)
#define SCR_STR 132                    // gather scratch row stride (uint32)
#define NSMEM ((4 * STAGE + 128 * SCR_STR) * 4)   // 118784 B
#define UVSMEM (4 * STAGE * 4)         // 51200 B
#define SL 1096                        // z1 slab stride (padded: conflict-free fill)
#define Z1U2 (16 * SL)                 // 17536
#define ESMEM ((Z1U2 + 4 * BSLAB) * 4) // 103936 B

__device__ __forceinline__ void store_slab(uint32_t* As, uint32_t* Bs, int am, int k2,
                                           uint2 ra, uint2 rb0, uint2 rb1) {
    As[(k2 + 0) * ASTR2 + am] = ra.x;
    As[(k2 + 1) * ASTR2 + am] = ra.y;
    Bs[(k2 + 0) * BSTR2 + am] = rb0.x;
    Bs[(k2 + 1) * BSTR2 + am] = rb0.y;
    Bs[(k2 + 0) * BSTR2 + am + 128] = rb1.x;
    Bs[(k2 + 1) * BSTR2 + am + 128] = rb1.y;
}
__device__ __forceinline__ void store_slab_b(uint32_t* Bs, int am, int k2,
                                             uint2 rb0, uint2 rb1) {
    Bs[(k2 + 0) * BSTR2 + am] = rb0.x;
    Bs[(k2 + 1) * BSTR2 + am] = rb0.y;
    Bs[(k2 + 0) * BSTR2 + am + 128] = rb1.x;
    Bs[(k2 + 1) * BSTR2 + am + 128] = rb1.y;
}

__device__ __forceinline__ void mma_slab(const uint32_t* As, const uint32_t* Bs,
                                         int wm, int wn, int lane,
                                         float c[2][8][4]) {
    int g = lane >> 2, t = lane & 3;
    uint32_t b0[8], b1[8];
#pragma unroll
    for (int nt = 0; nt < 8; nt++) {
        int C = wn * 64 + nt * 8 + g;
        b0[nt] = Bs[t * BSTR2 + C];
        b1[nt] = Bs[(t + 4) * BSTR2 + C];
    }
#pragma unroll
    for (int mt = 0; mt < 2; mt++) {
        int R = wm * 32 + mt * 16 + g;
        uint32_t a0 = As[t * ASTR2 + R];
        uint32_t a1 = As[t * ASTR2 + R + 8];
        uint32_t a2 = As[(t + 4) * ASTR2 + R];
        uint32_t a3 = As[(t + 4) * ASTR2 + R + 8];
#pragma unroll
        for (int nt = 0; nt < 8; nt++)
            mma16(c[mt][nt], a0, a1, a2, a3, b0[nt], b1[nt]);
    }
}

// ---------------------------------------------------------------- small kernels
__global__ void k_cvt_weights(const float* __restrict__ Wrel,
                              const float* __restrict__ Wroot,
                              const float* __restrict__ W1,
                              const float* __restrict__ W2) {
    const int NREL = LAYERS * 256 * 128;
    const int NW1 = 256 * 256;
    const int NW2 = 256 * 128;
    int i = blockIdx.x * blockDim.x + threadIdx.x;
    if (i < LAYERS * 512) g_statsf[i] = 0.f;
    if (i < NREL) {
        g_Wrel16[i] = pack_h2(Wrel[2 * i], Wrel[2 * i + 1]);
        g_Wroot16[i] = pack_h2(Wroot[2 * i], Wroot[2 * i + 1]);
    } else {
        int j = i - NREL;
        if (j < NW1) g_W116[j] = pack_h2(W1[2 * j], W1[2 * j + 1]);
        else if (j - NW1 < NW2) {
            int k = j - NW1;
            g_W216[k] = pack_h2(W2[2 * k], W2[2 * k + 1]);
        }
    }
}

__global__ void k_input_fc(const float* __restrict__ x, const float* __restrict__ Win) {
    int idx = blockIdx.x * blockDim.x + threadIdx.x;   // half2 units
    if (idx < N_NODES) g_deg[idx] = 0;
    if (idx >= N_NODES * 128) return;
    int node = idx >> 7, c0 = (idx & 127) * 2;
    float x0 = x[node * 2], x1 = x[node * 2 + 1];
    float h0 = x0 * Win[c0 * 2] + x1 * Win[c0 * 2 + 1];
    float h1 = x0 * Win[c0 * 2 + 2] + x1 * Win[c0 * 2 + 3];
    ((float2*)g_h)[idx] = make_float2(h0, h1);
    g_hh[idx] = pack_h2(h0, h1);
}

__global__ void k_csr_count(const int* __restrict__ ei) {
    int e = blockIdx.x * blockDim.x + threadIdx.x;
    if (e >= N_EDGES) return;
    atomicAdd(&g_deg[__ldg(ei + N_EDGES + e)], 1);
}

// multi-block scan: block-local exclusive + block sums
__global__ void k_scan1() {
    __shared__ int wsum[32];
    int tid = threadIdx.x, lane = tid & 31, wid = tid >> 5;
    int i = blockIdx.x * 1024 + tid;
    int v = (i < N_NODES) ? g_deg[i] : 0;
    int x = v;
#pragma unroll
    for (int d = 1; d < 32; d <<= 1) {
        int y = __shfl_up_sync(0xffffffffu, x, d);
        if (lane >= d) x += y;
    }
    if (lane == 31) wsum[wid] = x;
    __syncthreads();
    if (wid == 0) {
        int w = wsum[lane];
#pragma unroll
        for (int d = 1; d < 32; d <<= 1) {
            int y = __shfl_up_sync(0xffffffffu, w, d);
            if (lane >= d) w += y;
        }
        wsum[lane] = w;
    }
    __syncthreads();
    int incl = x + (wid > 0 ? wsum[wid - 1] : 0);
    if (i < N_NODES) g_off[i] = incl - v;       // block-local exclusive
    if (tid == 0) g_bsum[blockIdx.x] = wsum[31];
}

__global__ void k_scan2(int nblk) {
    if (threadIdx.x == 0) {
        int acc = 0;
        for (int b = 0; b < nblk; b++) { g_bsum2[b] = acc; acc += g_bsum[b]; }
        g_off[N_NODES] = acc;
    }
}

__global__ void k_scan3() {
    int i = blockIdx.x * blockDim.x + threadIdx.x;
    if (i >= N_NODES) return;
    int o = g_off[i] + g_bsum2[i >> 10];
    g_off[i] = o;
    g_pos[i] = o;
}

__global__ void k_csr_fill(const int* __restrict__ ei) {
    int e = blockIdx.x * blockDim.x + threadIdx.x;
    if (e >= N_EDGES) return;
    int d = __ldg(ei + N_EDGES + e);
    int p = atomicAdd(&g_pos[d], 1);
    g_srcs[p] = __ldg(ei + e);
}

// ---- BN finalize + apply fused (uint4/float4 vectorized) ----
__global__ void k_bn_apply(int layer, const float* __restrict__ gm,
                           const float* __restrict__ bt) {
    __shared__ float ssc[HID], ssh[HID];
    const float* stats = g_statsf + (size_t)layer * 512;
    int tid = threadIdx.x;
    if (tid < HID) {
        float mean = stats[tid] * (1.f / N_NODES);
        float var  = stats[HID + tid] * (1.f / N_NODES) - mean * mean;
        float rstd = rsqrtf(var + 1e-5f);
        float sc = rstd * __ldg(gm + tid);
        ssc[tid] = sc;
        ssh[tid] = __ldg(bt + tid) - mean * sc;
    }
    __syncthreads();
    int idx = blockIdx.x * blockDim.x + tid;   // uint4 units: N_NODES*32
    if (idx >= N_NODES * 32) return;
    int c0 = (idx & 31) * 8;
    uint4 o4 = ((const uint4*)g_outh)[idx];
    float4 h0 = ((const float4*)g_h)[idx * 2];
    float4 h1 = ((const float4*)g_h)[idx * 2 + 1];
    float2 f;
    f = unpack_h2(o4.x);
    h0.x += fmaxf(fmaf(f.x, ssc[c0 + 0], ssh[c0 + 0]), 0.f);
    h0.y += fmaxf(fmaf(f.y, ssc[c0 + 1], ssh[c0 + 1]), 0.f);
    f = unpack_h2(o4.y);
    h0.z += fmaxf(fmaf(f.x, ssc[c0 + 2], ssh[c0 + 2]), 0.f);
    h0.w += fmaxf(fmaf(f.y, ssc[c0 + 3], ssh[c0 + 3]), 0.f);
    f = unpack_h2(o4.z);
    h1.x += fmaxf(fmaf(f.x, ssc[c0 + 4], ssh[c0 + 4]), 0.f);
    h1.y += fmaxf(fmaf(f.y, ssc[c0 + 5], ssh[c0 + 5]), 0.f);
    f = unpack_h2(o4.w);
    h1.z += fmaxf(fmaf(f.x, ssc[c0 + 6], ssh[c0 + 6]), 0.f);
    h1.w += fmaxf(fmaf(f.y, ssc[c0 + 7], ssh[c0 + 7]), 0.f);
    ((float4*)g_h)[idx * 2] = h0;
    ((float4*)g_h)[idx * 2 + 1] = h1;
    uint4 hh;
    hh.x = pack_h2(h0.x, h0.y);
    hh.y = pack_h2(h0.z, h0.w);
    hh.z = pack_h2(h1.x, h1.y);
    hh.w = pack_h2(h1.z, h1.w);
    ((uint4*)g_hh)[idx] = hh;
}

// =================================================================
// node layer: phase 0 gathers agg (4-edge fp16 tree-reduce),
// BK=32 fp16 GEMM, fused BN stats epilogue.
// =================================================================
__global__ void __launch_bounds__(512, 1)
k_gemm_node(int layer, const float* __restrict__ br) {
    extern __shared__ uint32_t sm[];
    uint32_t* bufs = sm;
    uint32_t* scr  = sm + 4 * STAGE;
    int tid = threadIdx.x;
    int bm = blockIdx.x * 128;
    int lane = tid & 31, lq = lane >> 2, lr = lane & 3;
    int wid = tid >> 5, wm = wid & 3, wn = wid >> 2;
    int am = tid >> 2, aks = (tid & 3) * 4;
    int k2 = aks >> 1;
    int gr = bm + am;
    bool arow = gr < N_NODES;
    const uint32_t* Wr = g_Wrel16 + (size_t)layer * 256 * 128;
    const uint32_t* Wo = g_Wroot16 + (size_t)layer * 256 * 128;
    float* stats = g_statsf + (size_t)layer * 512;

    // ---- phase 0: gather (4-edge fp16 tree + fp32 accumulate) ----
    {
        const uint4* hp = (const uint4*)g_hh;
        for (int i = 0; i < 8; i++) {
            int row = wid * 8 + i;
            int node = bm + row;
            float acc[8] = {};
            if (node < N_NODES) {
                int beg = g_off[node], end = g_off[node + 1];
                int t = beg;
                for (; t + 3 < end; t += 4) {
                    int s0 = __ldg(&g_srcs[t]);
                    int s1 = __ldg(&g_srcs[t + 1]);
                    int s2 = __ldg(&g_srcs[t + 2]);
                    int s3 = __ldg(&g_srcs[t + 3]);
                    uint4 v0 = __ldg(hp + (size_t)s0 * 32 + lane);
                    uint4 v1 = __ldg(hp + (size_t)s1 * 32 + lane);
                    uint4 v2 = __ldg(hp + (size_t)s2 * 32 + lane);
                    uint4 v3 = __ldg(hp + (size_t)s3 * 32 + lane);
                    uint4 s01, s23, ssum;
                    s01.x = hadd2u(v0.x, v1.x); s01.y = hadd2u(v0.y, v1.y);
                    s01.z = hadd2u(v0.z, v1.z); s01.w = hadd2u(v0.w, v1.w);
                    s23.x = hadd2u(v2.x, v3.x); s23.y = hadd2u(v2.y, v3.y);
                    s23.z = hadd2u(v2.z, v3.z); s23.w = hadd2u(v2.w, v3.w);
                    ssum.x = hadd2u(s01.x, s23.x); ssum.y = hadd2u(s01.y, s23.y);
                    ssum.z = hadd2u(s01.z, s23.z); ssum.w = hadd2u(s01.w, s23.w);
                    acc_row(acc, ssum);
                }
                for (; t < end; t++) {
                    int s0 = __ldg(&g_srcs[t]);
                    uint4 v0 = __ldg(hp + (size_t)s0 * 32 + lane);
                    acc_row(acc, v0);
                }
            }
            uint4 o;
            o.x = pack_h2(acc[0], acc[1]);
            o.y = pack_h2(acc[2], acc[3]);
            o.z = pack_h2(acc[4], acc[5]);
            o.w = pack_h2(acc[6], acc[7]);
            *(uint4*)(scr + row * SCR_STR + lane * 4) = o;
        }
    }
    __syncthreads();

    // ---- mainloop: 16 stages x 32 K ----
    float c[2][8][4] = {};
    uint2 ra[2], rb0[2], rb1[2];
#pragma unroll
    for (int j = 0; j < 2; j++) {
        int hoff = j * 16 + aks;
        int kc2 = hoff >> 2;
        ra[j] = *(const uint2*)(scr + am * SCR_STR + (hoff >> 1));
        rb0[j] = __ldg((const uint2*)(Wr + (size_t)am * 128) + kc2);
        rb1[j] = __ldg((const uint2*)(Wr + (size_t)(am + 128) * 128) + kc2);
    }
    for (int st = 0; st < 16; st++) {
        int b = st & 1;
        uint32_t* s0 = bufs + b * 2 * STAGE;
        uint32_t* s1 = s0 + STAGE;
        store_slab(s0, s0 + ASLAB, am, k2, ra[0], rb0[0], rb1[0]);
        store_slab(s1, s1 + ASLAB, am, k2, ra[1], rb0[1], rb1[1]);
        uint2 na[2] = {ra[0], ra[1]}, nb0[2] = {rb0[0], rb0[1]}, nb1[2] = {rb1[0], rb1[1]};
        if (st < 15) {
#pragma unroll
            for (int j = 0; j < 2; j++) {
                int kk = 2 * st + 2 + j;
                int half = kk >> 4;
                int hoff = (kk & 15) * 16 + aks;
                int kc2 = hoff >> 2;
                if (half == 0) {
                    na[j] = *(const uint2*)(scr + am * SCR_STR + (hoff >> 1));
                    nb0[j] = __ldg((const uint2*)(Wr + (size_t)am * 128) + kc2);
                    nb1[j] = __ldg((const uint2*)(Wr + (size_t)(am + 128) * 128) + kc2);
                } else {
                    na[j] = arow ? __ldg((const uint2*)(g_hh + (size_t)gr * 128) + kc2)
                                 : make_uint2(0u, 0u);
                    nb0[j] = __ldg((const uint2*)(Wo + (size_t)am * 128) + kc2);
                    nb1[j] = __ldg((const uint2*)(Wo + (size_t)(am + 128) * 128) + kc2);
                }
            }
        }
        __syncthreads();
        mma_slab(s0, s0 + ASLAB, wm, wn, lane, c);
        mma_slab(s1, s1 + ASLAB, wm, wn, lane, c);
        ra[0] = na[0]; ra[1] = na[1];
        rb0[0] = nb0[0]; rb0[1] = nb0[1];
        rb1[0] = nb1[0]; rb1[1] = nb1[1];
    }

    // ---- epilogue ----
    float ps[8][2], pq[8][2];
#pragma unroll
    for (int nt = 0; nt < 8; nt++)
        ps[nt][0] = ps[nt][1] = pq[nt][0] = pq[nt][1] = 0.f;

#pragma unroll
    for (int mt = 0; mt < 2; mt++) {
        int row = bm + wm * 32 + mt * 16 + lq;
        bool v0 = row < N_NODES, v1 = (row + 8) < N_NODES;
#pragma unroll
        for (int nt = 0; nt < 8; nt++) {
            int col = wn * 64 + nt * 8 + lr * 2;
            float2 bb = __ldg((const float2*)(br + col));
            float o0 = c[mt][nt][0] + bb.x, o1 = c[mt][nt][1] + bb.y;
            float o2 = c[mt][nt][2] + bb.x, o3 = c[mt][nt][3] + bb.y;
            if (v0) {
                g_outh[(size_t)row * 128 + (col >> 1)] = pack_h2(o0, o1);
                ps[nt][0] += o0; pq[nt][0] += o0 * o0;
                ps[nt][1] += o1; pq[nt][1] += o1 * o1;
            }
            if (v1) {
                g_outh[(size_t)(row + 8) * 128 + (col >> 1)] = pack_h2(o2, o3);
                ps[nt][0] += o2; pq[nt][0] += o2 * o2;
                ps[nt][1] += o3; pq[nt][1] += o3 * o3;
            }
        }
    }
#pragma unroll
    for (int nt = 0; nt < 8; nt++)
#pragma unroll
        for (int u = 0; u < 2; u++) {
#pragma unroll
            for (int d = 4; d < 32; d <<= 1) {
                ps[nt][u] += __shfl_xor_sync(0xffffffffu, ps[nt][u], d);
                pq[nt][u] += __shfl_xor_sync(0xffffffffu, pq[nt][u], d);
            }
        }
    if (lq == 0) {
#pragma unroll
        for (int nt = 0; nt < 8; nt++) {
            int col = wn * 64 + nt * 8 + lr * 2;
            atomicAdd(&stats[col], ps[nt][0]);
            atomicAdd(&stats[col + 1], ps[nt][1]);
            atomicAdd(&stats[HID + col], pq[nt][0]);
            atomicAdd(&stats[HID + col + 1], pq[nt][1]);
        }
    }
}

// =================================================================
// UV precompute: U|V = h @ [W1a;W1b]^T ; grid (391, 2), ny: 0=U 1=V
// =================================================================
__global__ void __launch_bounds__(512, 1)
k_gemm_uv() {
    extern __shared__ uint32_t sm[];
    uint32_t* bufs = sm;
    int tid = threadIdx.x;
    int bm = blockIdx.x * 128;
    int ny = blockIdx.y;
    int lane = tid & 31, lq = lane >> 2, lr = lane & 3;
    int wid = tid >> 5, wm = wid & 3, wn = wid >> 2;
    int am = tid >> 2, aks = (tid & 3) * 4;
    int k2 = aks >> 1;
    int gr = bm + am;
    bool arow = gr < N_NODES;
    float c[2][8][4] = {};

    uint2 ra[2], rb0[2], rb1[2];
#pragma unroll
    for (int j = 0; j < 2; j++) {
        int kc2 = (j * 16 + aks) >> 2;
        ra[j] = arow ? __ldg((const uint2*)(g_hh + (size_t)gr * 128) + kc2)
                     : make_uint2(0u, 0u);
        rb0[j] = __ldg((const uint2*)(g_W116 + (size_t)am * 256) + ny * 64 + kc2);
        rb1[j] = __ldg((const uint2*)(g_W116 + (size_t)(am + 128) * 256) + ny * 64 + kc2);
    }
    for (int st = 0; st < 8; st++) {
        int b = st & 1;
        uint32_t* s0 = bufs + b * 2 * STAGE;
        uint32_t* s1 = s0 + STAGE;
        store_slab(s0, s0 + ASLAB, am, k2, ra[0], rb0[0], rb1[0]);
        store_slab(s1, s1 + ASLAB, am, k2, ra[1], rb0[1], rb1[1]);
        uint2 na[2] = {ra[0], ra[1]}, nb0[2] = {rb0[0], rb0[1]}, nb1[2] = {rb1[0], rb1[1]};
        if (st < 7) {
#pragma unroll
            for (int j = 0; j < 2; j++) {
                int kc2 = ((2 * st + 2 + j) * 16 + aks) >> 2;
                na[j] = arow ? __ldg((const uint2*)(g_hh + (size_t)gr * 128) + kc2)
                             : make_uint2(0u, 0u);
                nb0[j] = __ldg((const uint2*)(g_W116 + (size_t)am * 256) + ny * 64 + kc2);
                nb1[j] = __ldg((const uint2*)(g_W116 + (size_t)(am + 128) * 256) + ny * 64 + kc2);
            }
        }
        __syncthreads();
        mma_slab(s0, s0 + ASLAB, wm, wn, lane, c);
        mma_slab(s1, s1 + ASLAB, wm, wn, lane, c);
        ra[0] = na[0]; ra[1] = na[1];
        rb0[0] = nb0[0]; rb0[1] = nb0[1];
        rb1[0] = nb1[0]; rb1[1] = nb1[1];
    }
#pragma unroll
    for (int mt = 0; mt < 2; mt++) {
        int row = bm + wm * 32 + mt * 16 + lq;
#pragma unroll
        for (int nt = 0; nt < 8; nt++) {
            int col = wn * 64 + nt * 8 + lr * 2;
            if (row < N_NODES)
                g_uv[(size_t)row * 256 + ny * 128 + (col >> 1)] =
                    pack_h2(c[mt][nt][0], c[mt][nt][1]);
            if (row + 8 < N_NODES)
                g_uv[(size_t)(row + 8) * 256 + ny * 128 + (col >> 1)] =
                    pack_h2(c[mt][nt][2], c[mt][nt][3]);
        }
    }
}

// =================================================================
// fused edge MLP: z1 = relu(U[src]+V[dst]+b1) assembled in smem,
// then z1 @ W2^T, dot w3, sigmoid.
// =================================================================
__global__ void __launch_bounds__(512, 1)
k_edge_fused(const int* __restrict__ ei, const float* __restrict__ b1,
             const float* __restrict__ b2, const float* __restrict__ W3,
             const float* __restrict__ b3, float* __restrict__ dout) {
    extern __shared__ uint32_t sm[];
    uint32_t* z1sm = sm;                 // 16 slabs x SL
    uint32_t* bufs = sm + Z1U2;          // 4 x BSLAB
    __shared__ float sred[4][128];
    int tid = threadIdx.x;
    int bm = blockIdx.x * 128;
    int lane = tid & 31, lq = lane >> 2, lr = lane & 3;
    int wid = tid >> 5, wm = wid & 3, wn = wid >> 2;
    int am = tid >> 2, aks = (tid & 3) * 4;
    int k2 = aks >> 1;

    // ---- stage 0: assemble z1 in fragment layout ----
    {
        int row = tid >> 2, sub = tid & 3;
        int e = bm + row;
        bool val = e < N_EDGES;
        int nsrc = val ? __ldg(ei + e) : 0;
        int ndst = val ? __ldg(ei + N_EDGES + e) : 0;
        const uint4* up = (const uint4*)(g_uv + (size_t)nsrc * 256);
        const uint4* vp = (const uint4*)(g_uv + (size_t)ndst * 256 + 128);
#pragma unroll
        for (int q = 0; q < 4; q++) {
            int c2b = q * 32 + sub * 8;
            uint4 u0 = __ldg(up + (c2b >> 2));
            uint4 u1 = __ldg(up + (c2b >> 2) + 1);
            uint4 v0 = __ldg(vp + (c2b >> 2));
            uint4 v1 = __ldg(vp + (c2b >> 2) + 1);
            uint32_t uu[8] = {u0.x, u0.y, u0.z, u0.w, u1.x, u1.y, u1.z, u1.w};
            uint32_t vv[8] = {v0.x, v0.y, v0.z, v0.w, v1.x, v1.y, v1.z, v1.w};
            uint32_t* dst = z1sm + (q * 4 + sub) * SL + row;
#pragma unroll
            for (int j = 0; j < 8; j++) {
                int c2 = c2b + j;
                float2 fu = unpack_h2(uu[j]);
                float2 fv = unpack_h2(vv[j]);
                float2 bb = __ldg((const float2*)b1 + c2);
                dst[j * ASTR2] = pack_h2(fmaxf(fu.x + fv.x + bb.x, 0.f),
                                         fmaxf(fu.y + fv.y + bb.y, 0.f));
            }
        }
    }
    __syncthreads();

    // ---- stage 2: z1 @ W2^T (BK=32, B double-buffered) ----
    float c[2][8][4] = {};
    uint2 qb0[2], qb1[2];
#pragma unroll
    for (int j = 0; j < 2; j++) {
        int kc2 = (j * 16 + aks) >> 2;
        qb0[j] = __ldg((const uint2*)(g_W216 + (size_t)am * 128) + kc2);
        qb1[j] = __ldg((const uint2*)(g_W216 + (size_t)(am + 128) * 128) + kc2);
    }
    for (int st = 0; st < 8; st++) {
        int b = st & 1;
        uint32_t* B0 = bufs + b * 2 * BSLAB;
        uint32_t* B1 = B0 + BSLAB;
        store_slab_b(B0, am, k2, qb0[0], qb1[0]);
        store_slab_b(B1, am, k2, qb0[1], qb1[1]);
        uint2 n0[2] = {qb0[0], qb0[1]}, n1[2] = {qb1[0], qb1[1]};
        if (st < 7) {
#pragma unroll
            for (int j = 0; j < 2; j++) {
                int kc2 = ((2 * st + 2 + j) * 16 + aks) >> 2;
                n0[j] = __ldg((const uint2*)(g_W216 + (size_t)am * 128) + kc2);
                n1[j] = __ldg((const uint2*)(g_W216 + (size_t)(am + 128) * 128) + kc2);
            }
        }
        __syncthreads();
        mma_slab(z1sm + (2 * st) * SL, B0, wm, wn, lane, c);
        mma_slab(z1sm + (2 * st + 1) * SL, B1, wm, wn, lane, c);
        qb0[0] = n0[0]; qb0[1] = n0[1];
        qb1[0] = n1[0]; qb1[1] = n1[1];
    }

#pragma unroll
    for (int mt = 0; mt < 2; mt++) {
        float p0 = 0.f, p1 = 0.f;
#pragma unroll
        for (int nt = 0; nt < 8; nt++) {
            int col = wn * 64 + nt * 8 + lr * 2;
            float2 bb = __ldg((const float2*)(b2 + col));
            float2 ww = __ldg((const float2*)(W3 + col));
            p0 = fmaf(fmaxf(c[mt][nt][0] + bb.x, 0.f), ww.x, p0);
            p0 = fmaf(fmaxf(c[mt][nt][1] + bb.y, 0.f), ww.y, p0);
            p1 = fmaf(fmaxf(c[mt][nt][2] + bb.x, 0.f), ww.x, p1);
            p1 = fmaf(fmaxf(c[mt][nt][3] + bb.y, 0.f), ww.y, p1);
        }
        p0 += __shfl_xor_sync(0xffffffffu, p0, 1);
        p0 += __shfl_xor_sync(0xffffffffu, p0, 2);
        p1 += __shfl_xor_sync(0xffffffffu, p1, 1);
        p1 += __shfl_xor_sync(0xffffffffu, p1, 2);
        if (lr == 0) {
            sred[wn][wm * 32 + mt * 16 + lq] = p0;
            sred[wn][wm * 32 + mt * 16 + lq + 8] = p1;
        }
    }
    __syncthreads();
    if (tid < 128) {
        int gr = bm + tid;
        if (gr < N_EDGES) {
            float s = sred[0][tid] + sred[1][tid] + sred[2][tid] + sred[3][tid] + __ldg(b3);
            dout[gr] = 1.f / (1.f + expf(-s));
        }
    }
}

// ---------------------------------------------------------------- launch
extern "C" void kernel_launch(void* const* d_in, const int* in_sizes, int n_in,
                              void* d_out, int out_size) {
    const float* x     = (const float*)d_in[0];
    const int*   ei    = (const int*)  d_in[1];
    const float* Win   = (const float*)d_in[2];
    const float* Wrel  = (const float*)d_in[3];
    const float* brel  = (const float*)d_in[4];
    const float* Wroot = (const float*)d_in[5];
    const float* gamma = (const float*)d_in[6];
    const float* beta  = (const float*)d_in[7];
    const float* W1    = (const float*)d_in[8];
    const float* b1    = (const float*)d_in[9];
    const float* W2    = (const float*)d_in[10];
    const float* b2    = (const float*)d_in[11];
    const float* W3    = (const float*)d_in[12];
    const float* b3    = (const float*)d_in[13];
    float* out = (float*)d_out;

    cudaFuncSetAttribute(k_gemm_node, cudaFuncAttributeMaxDynamicSharedMemorySize, NSMEM);
    cudaFuncSetAttribute(k_gemm_uv,   cudaFuncAttributeMaxDynamicSharedMemorySize, UVSMEM);
    cudaFuncSetAttribute(k_edge_fused, cudaFuncAttributeMaxDynamicSharedMemorySize, ESMEM);

    int ncvt = LAYERS * 256 * 128 + 256 * 256 + 256 * 128;
    k_cvt_weights<<<(ncvt + 255) / 256, 256>>>(Wrel, Wroot, W1, W2);
    k_input_fc<<<(N_NODES * 128 + 255) / 256, 256>>>(x, Win);
    k_csr_count<<<(N_EDGES + 255) / 256, 256>>>(ei);
    int nblk = (N_NODES + 1023) / 1024;   // 49
    k_scan1<<<nblk, 1024>>>();
    k_scan2<<<1, 32>>>(nblk);
    k_scan3<<<(N_NODES + 255) / 256, 256>>>();
    k_csr_fill<<<(N_EDGES + 255) / 256, 256>>>(ei);

    int node_grid = (N_NODES + 127) / 128;     // 391
    for (int l = 0; l < LAYERS; l++) {
        k_gemm_node<<<node_grid, 512, NSMEM>>>(l, brel + (size_t)l * HID);
        k_bn_apply<<<(N_NODES * 32 + 255) / 256, 256>>>(
            l, gamma + (size_t)l * HID, beta + (size_t)l * HID);
    }

    dim3 uv_grid(node_grid, 2);
    k_gemm_uv<<<uv_grid, 512, UVSMEM>>>();
    int edge_grid = (N_EDGES + 127) / 128;     // 3907
    k_edge_fused<<<edge_grid, 512, ESMEM>>>(ei, b1, b2, W3, b3, out);
}

// round 16
// speedup vs baseline: 1.5947x; 1.0229x over previous
#include <cuda_runtime.h>
#include <cuda_fp16.h>
#include <cstdint>
#include <math.h>

#define N_NODES 50000
#define N_EDGES 500000
#define HID 256
#define LAYERS 15

// ---------------------------------------------------------------- scratch
__device__ float    g_h   [(size_t)N_NODES * HID];    // fp32 residual carry
__device__ uint32_t g_hh  [(size_t)N_NODES * 128];    // h as half2
__device__ uint32_t g_outh[(size_t)N_NODES * 128];    // pre-BN out as half2
__device__ uint32_t g_uv  [(size_t)N_NODES * 256];    // U|V per node (half2)
__device__ float    g_statsf[LAYERS * 512];           // per-layer BN sum/sumsq
// fp16 weights
__device__ uint32_t g_Wrel16 [LAYERS * 256 * 128];
__device__ uint32_t g_Wroot16[LAYERS * 256 * 128];
__device__ uint32_t g_W116[256 * 256];
__device__ uint32_t g_W216[256 * 128];
// CSR
__device__ int g_deg[N_NODES];
__device__ int g_off[N_NODES + 1];
__device__ int g_pos[N_NODES];
__device__ int g_srcs[N_EDGES];
__device__ int g_bsum[64];
__device__ int g_bsum2[64];

// ---------------------------------------------------------------- helpers
__device__ __forceinline__ uint32_t pack_h2(float x, float y) {
    __half2 h = __float22half2_rn(make_float2(x, y));
    return *(uint32_t*)&h;
}
__device__ __forceinline__ float2 unpack_h2(uint32_t u) {
    return __half22float2(*(__half2*)&u);
}
__device__ __forceinline__ uint32_t hadd2u(uint32_t a, uint32_t b) {
    __half2 r = __hadd2(*(__half2*)&a, *(__half2*)&b);
    return *(uint32_t*)&r;
}
__device__ __forceinline__ void mma16(float* c, uint32_t a0, uint32_t a1,
                                      uint32_t a2, uint32_t a3,
                                      uint32_t b0, uint32_t b1) {
    asm volatile(
        "mma.sync.aligned.m16n8k16.row.col.f32.f16.f16.f32 "
        "{%0,%1,%2,%3}, {%4,%5,%6,%7}, {%8,%9}, {%0,%1,%2,%3};"
        : "+f"(c[0]), "+f"(c[1]), "+f"(c[2]), "+f"(c[3])
        : "r"(a0), "r"(a1), "r"(a2), "r"(a3), "r"(b0), "r"(b1));
}
__device__ __forceinline__ void acc_row(float* acc, uint4 v) {
    float2 f;
    f = unpack_h2(v.x); acc[0] += f.x; acc[1] += f.y;
    f = unpack_h2(v.y); acc[2] += f.x; acc[3] += f.y;
    f = unpack_h2(v.z); acc[4] += f.x; acc[5] += f.y;
    f = unpack_h2(v.w); acc[6] += f.x; acc[7] += f.y;
}
__device__ __forceinline__ uint4 tree4(uint4 v0, uint4 v1, uint4 v2, uint4 v3) {
    uint4 s01, s23, s;
    s01.x = hadd2u(v0.x, v1.x); s01.y = hadd2u(v0.y, v1.y);
    s01.z = hadd2u(v0.z, v1.z); s01.w = hadd2u(v0.w, v1.w);
    s23.x = hadd2u(v2.x, v3.x); s23.y = hadd2u(v2.y, v3.y);
    s23.z = hadd2u(v2.z, v3.z); s23.w = hadd2u(v2.w, v3.w);
    s.x = hadd2u(s01.x, s23.x); s.y = hadd2u(s01.y, s23.y);
    s.z = hadd2u(s01.z, s23.z); s.w = hadd2u(s01.w, s23.w);
    return s;
}

// smem (half2 units):  A2[k2 8][row 128]  B2[k2 8][col 256], strides ≡ 8 mod 32
#define ASTR2 136
#define BSTR2 264
#define ASLAB (8 * ASTR2)              // 1088
#define BSLAB (8 * BSTR2)              // 2112
#define STAGE (ASLAB + BSLAB)          // 3200 uints (one 16-K slab A+B)
#define SCR_STR 132                    // gather scratch row stride (uint32)
#define NSMEM ((4 * STAGE + 128 * SCR_STR) * 4)   // 118784 B
#define UVSMEM (4 * STAGE * 4)         // 51200 B
#define SL 1096                        // z1 slab stride (padded: conflict-free fill)
#define Z1U2 (16 * SL)                 // 17536
#define ESMEM ((Z1U2 + 4 * BSLAB) * 4) // 103936 B

__device__ __forceinline__ void store_slab(uint32_t* As, uint32_t* Bs, int am, int k2,
                                           uint2 ra, uint2 rb0, uint2 rb1) {
    As[(k2 + 0) * ASTR2 + am] = ra.x;
    As[(k2 + 1) * ASTR2 + am] = ra.y;
    Bs[(k2 + 0) * BSTR2 + am] = rb0.x;
    Bs[(k2 + 1) * BSTR2 + am] = rb0.y;
    Bs[(k2 + 0) * BSTR2 + am + 128] = rb1.x;
    Bs[(k2 + 1) * BSTR2 + am + 128] = rb1.y;
}
__device__ __forceinline__ void store_slab_b(uint32_t* Bs, int am, int k2,
                                             uint2 rb0, uint2 rb1) {
    Bs[(k2 + 0) * BSTR2 + am] = rb0.x;
    Bs[(k2 + 1) * BSTR2 + am] = rb0.y;
    Bs[(k2 + 0) * BSTR2 + am + 128] = rb1.x;
    Bs[(k2 + 1) * BSTR2 + am + 128] = rb1.y;
}

__device__ __forceinline__ void mma_slab(const uint32_t* As, const uint32_t* Bs,
                                         int wm, int wn, int lane,
                                         float c[2][8][4]) {
    int g = lane >> 2, t = lane & 3;
    uint32_t b0[8], b1[8];
#pragma unroll
    for (int nt = 0; nt < 8; nt++) {
        int C = wn * 64 + nt * 8 + g;
        b0[nt] = Bs[t * BSTR2 + C];
        b1[nt] = Bs[(t + 4) * BSTR2 + C];
    }
#pragma unroll
    for (int mt = 0; mt < 2; mt++) {
        int R = wm * 32 + mt * 16 + g;
        uint32_t a0 = As[t * ASTR2 + R];
        uint32_t a1 = As[t * ASTR2 + R + 8];
        uint32_t a2 = As[(t + 4) * ASTR2 + R];
        uint32_t a3 = As[(t + 4) * ASTR2 + R + 8];
#pragma unroll
        for (int nt = 0; nt < 8; nt++)
            mma16(c[mt][nt], a0, a1, a2, a3, b0[nt], b1[nt]);
    }
}

// ---------------------------------------------------------------- small kernels
__global__ void k_cvt_weights(const float* __restrict__ Wrel,
                              const float* __restrict__ Wroot,
                              const float* __restrict__ W1,
                              const float* __restrict__ W2) {
    const int NREL = LAYERS * 256 * 128;
    const int NW1 = 256 * 256;
    const int NW2 = 256 * 128;
    int i = blockIdx.x * blockDim.x + threadIdx.x;
    if (i < LAYERS * 512) g_statsf[i] = 0.f;
    if (i < NREL) {
        g_Wrel16[i] = pack_h2(Wrel[2 * i], Wrel[2 * i + 1]);
        g_Wroot16[i] = pack_h2(Wroot[2 * i], Wroot[2 * i + 1]);
    } else {
        int j = i - NREL;
        if (j < NW1) g_W116[j] = pack_h2(W1[2 * j], W1[2 * j + 1]);
        else if (j - NW1 < NW2) {
            int k = j - NW1;
            g_W216[k] = pack_h2(W2[2 * k], W2[2 * k + 1]);
        }
    }
}

__global__ void k_input_fc(const float* __restrict__ x, const float* __restrict__ Win) {
    int idx = blockIdx.x * blockDim.x + threadIdx.x;   // half2 units
    if (idx < N_NODES) g_deg[idx] = 0;
    if (idx >= N_NODES * 128) return;
    int node = idx >> 7, c0 = (idx & 127) * 2;
    float x0 = x[node * 2], x1 = x[node * 2 + 1];
    float h0 = x0 * Win[c0 * 2] + x1 * Win[c0 * 2 + 1];
    float h1 = x0 * Win[c0 * 2 + 2] + x1 * Win[c0 * 2 + 3];
    ((float2*)g_h)[idx] = make_float2(h0, h1);
    g_hh[idx] = pack_h2(h0, h1);
}

__global__ void k_csr_count(const int* __restrict__ ei) {
    int e = blockIdx.x * blockDim.x + threadIdx.x;
    if (e >= N_EDGES) return;
    atomicAdd(&g_deg[__ldg(ei + N_EDGES + e)], 1);
}

// multi-block scan: block-local exclusive + block sums
__global__ void k_scan1() {
    __shared__ int wsum[32];
    int tid = threadIdx.x, lane = tid & 31, wid = tid >> 5;
    int i = blockIdx.x * 1024 + tid;
    int v = (i < N_NODES) ? g_deg[i] : 0;
    int x = v;
#pragma unroll
    for (int d = 1; d < 32; d <<= 1) {
        int y = __shfl_up_sync(0xffffffffu, x, d);
        if (lane >= d) x += y;
    }
    if (lane == 31) wsum[wid] = x;
    __syncthreads();
    if (wid == 0) {
        int w = wsum[lane];
#pragma unroll
        for (int d = 1; d < 32; d <<= 1) {
            int y = __shfl_up_sync(0xffffffffu, w, d);
            if (lane >= d) w += y;
        }
        wsum[lane] = w;
    }
    __syncthreads();
    int incl = x + (wid > 0 ? wsum[wid - 1] : 0);
    if (i < N_NODES) g_off[i] = incl - v;       // block-local exclusive
    if (tid == 0) g_bsum[blockIdx.x] = wsum[31];
}

__global__ void k_scan2(int nblk) {
    if (threadIdx.x == 0) {
        int acc = 0;
        for (int b = 0; b < nblk; b++) { g_bsum2[b] = acc; acc += g_bsum[b]; }
        g_off[N_NODES] = acc;
    }
}

__global__ void k_scan3() {
    int i = blockIdx.x * blockDim.x + threadIdx.x;
    if (i >= N_NODES) return;
    int o = g_off[i] + g_bsum2[i >> 10];
    g_off[i] = o;
    g_pos[i] = o;
}

__global__ void k_csr_fill(const int* __restrict__ ei) {
    int e = blockIdx.x * blockDim.x + threadIdx.x;
    if (e >= N_EDGES) return;
    int d = __ldg(ei + N_EDGES + e);
    int p = atomicAdd(&g_pos[d], 1);
    g_srcs[p] = __ldg(ei + e);
}

// ---- BN finalize + apply fused (uint4/float4 vectorized) ----
__global__ void k_bn_apply(int layer, const float* __restrict__ gm,
                           const float* __restrict__ bt) {
    __shared__ float ssc[HID], ssh[HID];
    const float* stats = g_statsf + (size_t)layer * 512;
    int tid = threadIdx.x;
    if (tid < HID) {
        float mean = stats[tid] * (1.f / N_NODES);
        float var  = stats[HID + tid] * (1.f / N_NODES) - mean * mean;
        float rstd = rsqrtf(var + 1e-5f);
        float sc = rstd * __ldg(gm + tid);
        ssc[tid] = sc;
        ssh[tid] = __ldg(bt + tid) - mean * sc;
    }
    __syncthreads();
    int idx = blockIdx.x * blockDim.x + tid;   // uint4 units: N_NODES*32
    if (idx >= N_NODES * 32) return;
    int c0 = (idx & 31) * 8;
    uint4 o4 = ((const uint4*)g_outh)[idx];
    float4 h0 = ((const float4*)g_h)[idx * 2];
    float4 h1 = ((const float4*)g_h)[idx * 2 + 1];
    float2 f;
    f = unpack_h2(o4.x);
    h0.x += fmaxf(fmaf(f.x, ssc[c0 + 0], ssh[c0 + 0]), 0.f);
    h0.y += fmaxf(fmaf(f.y, ssc[c0 + 1], ssh[c0 + 1]), 0.f);
    f = unpack_h2(o4.y);
    h0.z += fmaxf(fmaf(f.x, ssc[c0 + 2], ssh[c0 + 2]), 0.f);
    h0.w += fmaxf(fmaf(f.y, ssc[c0 + 3], ssh[c0 + 3]), 0.f);
    f = unpack_h2(o4.z);
    h1.x += fmaxf(fmaf(f.x, ssc[c0 + 4], ssh[c0 + 4]), 0.f);
    h1.y += fmaxf(fmaf(f.y, ssc[c0 + 5], ssh[c0 + 5]), 0.f);
    f = unpack_h2(o4.w);
    h1.z += fmaxf(fmaf(f.x, ssc[c0 + 6], ssh[c0 + 6]), 0.f);
    h1.w += fmaxf(fmaf(f.y, ssc[c0 + 7], ssh[c0 + 7]), 0.f);
    ((float4*)g_h)[idx * 2] = h0;
    ((float4*)g_h)[idx * 2 + 1] = h1;
    uint4 hh;
    hh.x = pack_h2(h0.x, h0.y);
    hh.y = pack_h2(h0.z, h0.w);
    hh.z = pack_h2(h1.x, h1.y);
    hh.w = pack_h2(h1.z, h1.w);
    ((uint4*)g_hh)[idx] = hh;
}

// =================================================================
// node layer: phase 0 gathers agg (8-edge: two 4-edge fp16 trees),
// BK=32 fp16 GEMM, fused BN stats epilogue.
// =================================================================
__global__ void __launch_bounds__(512, 1)
k_gemm_node(int layer, const float* __restrict__ br) {
    extern __shared__ uint32_t sm[];
    uint32_t* bufs = sm;
    uint32_t* scr  = sm + 4 * STAGE;
    int tid = threadIdx.x;
    int bm = blockIdx.x * 128;
    int lane = tid & 31, lq = lane >> 2, lr = lane & 3;
    int wid = tid >> 5, wm = wid & 3, wn = wid >> 2;
    int am = tid >> 2, aks = (tid & 3) * 4;
    int k2 = aks >> 1;
    int gr = bm + am;
    bool arow = gr < N_NODES;
    const uint32_t* Wr = g_Wrel16 + (size_t)layer * 256 * 128;
    const uint32_t* Wo = g_Wroot16 + (size_t)layer * 256 * 128;
    float* stats = g_statsf + (size_t)layer * 512;

    // ---- phase 0: gather (8-edge unroll, two fp16 trees) ----
    {
        const uint4* hp = (const uint4*)g_hh;
        for (int i = 0; i < 8; i++) {
            int row = wid * 8 + i;
            int node = bm + row;
            float acc[8] = {};
            if (node < N_NODES) {
                int beg = g_off[node], end = g_off[node + 1];
                int t = beg;
                for (; t + 7 < end; t += 8) {
                    int s0 = __ldg(&g_srcs[t]);
                    int s1 = __ldg(&g_srcs[t + 1]);
                    int s2 = __ldg(&g_srcs[t + 2]);
                    int s3 = __ldg(&g_srcs[t + 3]);
                    int s4 = __ldg(&g_srcs[t + 4]);
                    int s5 = __ldg(&g_srcs[t + 5]);
                    int s6 = __ldg(&g_srcs[t + 6]);
                    int s7 = __ldg(&g_srcs[t + 7]);
                    uint4 v0 = __ldg(hp + (size_t)s0 * 32 + lane);
                    uint4 v1 = __ldg(hp + (size_t)s1 * 32 + lane);
                    uint4 v2 = __ldg(hp + (size_t)s2 * 32 + lane);
                    uint4 v3 = __ldg(hp + (size_t)s3 * 32 + lane);
                    uint4 v4 = __ldg(hp + (size_t)s4 * 32 + lane);
                    uint4 v5 = __ldg(hp + (size_t)s5 * 32 + lane);
                    uint4 v6 = __ldg(hp + (size_t)s6 * 32 + lane);
                    uint4 v7 = __ldg(hp + (size_t)s7 * 32 + lane);
                    acc_row(acc, tree4(v0, v1, v2, v3));
                    acc_row(acc, tree4(v4, v5, v6, v7));
                }
                for (; t + 3 < end; t += 4) {
                    int s0 = __ldg(&g_srcs[t]);
                    int s1 = __ldg(&g_srcs[t + 1]);
                    int s2 = __ldg(&g_srcs[t + 2]);
                    int s3 = __ldg(&g_srcs[t + 3]);
                    uint4 v0 = __ldg(hp + (size_t)s0 * 32 + lane);
                    uint4 v1 = __ldg(hp + (size_t)s1 * 32 + lane);
                    uint4 v2 = __ldg(hp + (size_t)s2 * 32 + lane);
                    uint4 v3 = __ldg(hp + (size_t)s3 * 32 + lane);
                    acc_row(acc, tree4(v0, v1, v2, v3));
                }
                for (; t < end; t++) {
                    int s0 = __ldg(&g_srcs[t]);
                    uint4 v0 = __ldg(hp + (size_t)s0 * 32 + lane);
                    acc_row(acc, v0);
                }
            }
            uint4 o;
            o.x = pack_h2(acc[0], acc[1]);
            o.y = pack_h2(acc[2], acc[3]);
            o.z = pack_h2(acc[4], acc[5]);
            o.w = pack_h2(acc[6], acc[7]);
            *(uint4*)(scr + row * SCR_STR + lane * 4) = o;
        }
    }
    __syncthreads();

    // ---- mainloop: 16 stages x 32 K ----
    float c[2][8][4] = {};
    uint2 ra[2], rb0[2], rb1[2];
#pragma unroll
    for (int j = 0; j < 2; j++) {
        int hoff = j * 16 + aks;
        int kc2 = hoff >> 2;
        ra[j] = *(const uint2*)(scr + am * SCR_STR + (hoff >> 1));
        rb0[j] = __ldg((const uint2*)(Wr + (size_t)am * 128) + kc2);
        rb1[j] = __ldg((const uint2*)(Wr + (size_t)(am + 128) * 128) + kc2);
    }
    for (int st = 0; st < 16; st++) {
        int b = st & 1;
        uint32_t* s0 = bufs + b * 2 * STAGE;
        uint32_t* s1 = s0 + STAGE;
        store_slab(s0, s0 + ASLAB, am, k2, ra[0], rb0[0], rb1[0]);
        store_slab(s1, s1 + ASLAB, am, k2, ra[1], rb0[1], rb1[1]);
        uint2 na[2] = {ra[0], ra[1]}, nb0[2] = {rb0[0], rb0[1]}, nb1[2] = {rb1[0], rb1[1]};
        if (st < 15) {
#pragma unroll
            for (int j = 0; j < 2; j++) {
                int kk = 2 * st + 2 + j;
                int half = kk >> 4;
                int hoff = (kk & 15) * 16 + aks;
                int kc2 = hoff >> 2;
                if (half == 0) {
                    na[j] = *(const uint2*)(scr + am * SCR_STR + (hoff >> 1));
                    nb0[j] = __ldg((const uint2*)(Wr + (size_t)am * 128) + kc2);
                    nb1[j] = __ldg((const uint2*)(Wr + (size_t)(am + 128) * 128) + kc2);
                } else {
                    na[j] = arow ? __ldg((const uint2*)(g_hh + (size_t)gr * 128) + kc2)
                                 : make_uint2(0u, 0u);
                    nb0[j] = __ldg((const uint2*)(Wo + (size_t)am * 128) + kc2);
                    nb1[j] = __ldg((const uint2*)(Wo + (size_t)(am + 128) * 128) + kc2);
                }
            }
        }
        __syncthreads();
        mma_slab(s0, s0 + ASLAB, wm, wn, lane, c);
        mma_slab(s1, s1 + ASLAB, wm, wn, lane, c);
        ra[0] = na[0]; ra[1] = na[1];
        rb0[0] = nb0[0]; rb0[1] = nb0[1];
        rb1[0] = nb1[0]; rb1[1] = nb1[1];
    }

    // ---- epilogue ----
    float ps[8][2], pq[8][2];
#pragma unroll
    for (int nt = 0; nt < 8; nt++)
        ps[nt][0] = ps[nt][1] = pq[nt][0] = pq[nt][1] = 0.f;

#pragma unroll
    for (int mt = 0; mt < 2; mt++) {
        int row = bm + wm * 32 + mt * 16 + lq;
        bool v0 = row < N_NODES, v1 = (row + 8) < N_NODES;
#pragma unroll
        for (int nt = 0; nt < 8; nt++) {
            int col = wn * 64 + nt * 8 + lr * 2;
            float2 bb = __ldg((const float2*)(br + col));
            float o0 = c[mt][nt][0] + bb.x, o1 = c[mt][nt][1] + bb.y;
            float o2 = c[mt][nt][2] + bb.x, o3 = c[mt][nt][3] + bb.y;
            if (v0) {
                g_outh[(size_t)row * 128 + (col >> 1)] = pack_h2(o0, o1);
                ps[nt][0] += o0; pq[nt][0] += o0 * o0;
                ps[nt][1] += o1; pq[nt][1] += o1 * o1;
            }
            if (v1) {
                g_outh[(size_t)(row + 8) * 128 + (col >> 1)] = pack_h2(o2, o3);
                ps[nt][0] += o2; pq[nt][0] += o2 * o2;
                ps[nt][1] += o3; pq[nt][1] += o3 * o3;
            }
        }
    }
#pragma unroll
    for (int nt = 0; nt < 8; nt++)
#pragma unroll
        for (int u = 0; u < 2; u++) {
#pragma unroll
            for (int d = 4; d < 32; d <<= 1) {
                ps[nt][u] += __shfl_xor_sync(0xffffffffu, ps[nt][u], d);
                pq[nt][u] += __shfl_xor_sync(0xffffffffu, pq[nt][u], d);
            }
        }
    if (lq == 0) {
#pragma unroll
        for (int nt = 0; nt < 8; nt++) {
            int col = wn * 64 + nt * 8 + lr * 2;
            atomicAdd(&stats[col], ps[nt][0]);
            atomicAdd(&stats[col + 1], ps[nt][1]);
            atomicAdd(&stats[HID + col], pq[nt][0]);
            atomicAdd(&stats[HID + col + 1], pq[nt][1]);
        }
    }
}

// =================================================================
// UV precompute: U|V = h @ [W1a;W1b]^T ; grid (391, 2), ny: 0=U 1=V
// =================================================================
__global__ void __launch_bounds__(512, 1)
k_gemm_uv() {
    extern __shared__ uint32_t sm[];
    uint32_t* bufs = sm;
    int tid = threadIdx.x;
    int bm = blockIdx.x * 128;
    int ny = blockIdx.y;
    int lane = tid & 31, lq = lane >> 2, lr = lane & 3;
    int wid = tid >> 5, wm = wid & 3, wn = wid >> 2;
    int am = tid >> 2, aks = (tid & 3) * 4;
    int k2 = aks >> 1;
    int gr = bm + am;
    bool arow = gr < N_NODES;
    float c[2][8][4] = {};

    uint2 ra[2], rb0[2], rb1[2];
#pragma unroll
    for (int j = 0; j < 2; j++) {
        int kc2 = (j * 16 + aks) >> 2;
        ra[j] = arow ? __ldg((const uint2*)(g_hh + (size_t)gr * 128) + kc2)
                     : make_uint2(0u, 0u);
        rb0[j] = __ldg((const uint2*)(g_W116 + (size_t)am * 256) + ny * 64 + kc2);
        rb1[j] = __ldg((const uint2*)(g_W116 + (size_t)(am + 128) * 256) + ny * 64 + kc2);
    }
    for (int st = 0; st < 8; st++) {
        int b = st & 1;
        uint32_t* s0 = bufs + b * 2 * STAGE;
        uint32_t* s1 = s0 + STAGE;
        store_slab(s0, s0 + ASLAB, am, k2, ra[0], rb0[0], rb1[0]);
        store_slab(s1, s1 + ASLAB, am, k2, ra[1], rb0[1], rb1[1]);
        uint2 na[2] = {ra[0], ra[1]}, nb0[2] = {rb0[0], rb0[1]}, nb1[2] = {rb1[0], rb1[1]};
        if (st < 7) {
#pragma unroll
            for (int j = 0; j < 2; j++) {
                int kc2 = ((2 * st + 2 + j) * 16 + aks) >> 2;
                na[j] = arow ? __ldg((const uint2*)(g_hh + (size_t)gr * 128) + kc2)
                             : make_uint2(0u, 0u);
                nb0[j] = __ldg((const uint2*)(g_W116 + (size_t)am * 256) + ny * 64 + kc2);
                nb1[j] = __ldg((const uint2*)(g_W116 + (size_t)(am + 128) * 256) + ny * 64 + kc2);
            }
        }
        __syncthreads();
        mma_slab(s0, s0 + ASLAB, wm, wn, lane, c);
        mma_slab(s1, s1 + ASLAB, wm, wn, lane, c);
        ra[0] = na[0]; ra[1] = na[1];
        rb0[0] = nb0[0]; rb0[1] = nb0[1];
        rb1[0] = nb1[0]; rb1[1] = nb1[1];
    }
#pragma unroll
    for (int mt = 0; mt < 2; mt++) {
        int row = bm + wm * 32 + mt * 16 + lq;
#pragma unroll
        for (int nt = 0; nt < 8; nt++) {
            int col = wn * 64 + nt * 8 + lr * 2;
            if (row < N_NODES)
                g_uv[(size_t)row * 256 + ny * 128 + (col >> 1)] =
                    pack_h2(c[mt][nt][0], c[mt][nt][1]);
            if (row + 8 < N_NODES)
                g_uv[(size_t)(row + 8) * 256 + ny * 128 + (col >> 1)] =
                    pack_h2(c[mt][nt][2], c[mt][nt][3]);
        }
    }
}

// =================================================================
// fused edge MLP: z1 = relu(U[src]+V[dst]+b1) assembled in smem,
// then z1 @ W2^T, dot w3, sigmoid.
// =================================================================
__global__ void __launch_bounds__(512, 1)
k_edge_fused(const int* __restrict__ ei, const float* __restrict__ b1,
             const float* __restrict__ b2, const float* __restrict__ W3,
             const float* __restrict__ b3, float* __restrict__ dout) {
    extern __shared__ uint32_t sm[];
    uint32_t* z1sm = sm;                 // 16 slabs x SL
    uint32_t* bufs = sm + Z1U2;          // 4 x BSLAB
    __shared__ float sred[4][128];
    int tid = threadIdx.x;
    int bm = blockIdx.x * 128;
    int lane = tid & 31, lq = lane >> 2, lr = lane & 3;
    int wid = tid >> 5, wm = wid & 3, wn = wid >> 2;
    int am = tid >> 2, aks = (tid & 3) * 4;
    int k2 = aks >> 1;

    // ---- stage 0: assemble z1 in fragment layout ----
    {
        int row = tid >> 2, sub = tid & 3;
        int e = bm + row;
        bool val = e < N_EDGES;
        int nsrc = val ? __ldg(ei + e) : 0;
        int ndst = val ? __ldg(ei + N_EDGES + e) : 0;
        const uint4* up = (const uint4*)(g_uv + (size_t)nsrc * 256);
        const uint4* vp = (const uint4*)(g_uv + (size_t)ndst * 256 + 128);
#pragma unroll
        for (int q = 0; q < 4; q++) {
            int c2b = q * 32 + sub * 8;
            uint4 u0 = __ldg(up + (c2b >> 2));
            uint4 u1 = __ldg(up + (c2b >> 2) + 1);
            uint4 v0 = __ldg(vp + (c2b >> 2));
            uint4 v1 = __ldg(vp + (c2b >> 2) + 1);
            uint32_t uu[8] = {u0.x, u0.y, u0.z, u0.w, u1.x, u1.y, u1.z, u1.w};
            uint32_t vv[8] = {v0.x, v0.y, v0.z, v0.w, v1.x, v1.y, v1.z, v1.w};
            uint32_t* dst = z1sm + (q * 4 + sub) * SL + row;
#pragma unroll
            for (int j = 0; j < 8; j++) {
                int c2 = c2b + j;
                float2 fu = unpack_h2(uu[j]);
                float2 fv = unpack_h2(vv[j]);
                float2 bb = __ldg((const float2*)b1 + c2);
                dst[j * ASTR2] = pack_h2(fmaxf(fu.x + fv.x + bb.x, 0.f),
                                         fmaxf(fu.y + fv.y + bb.y, 0.f));
            }
        }
    }
    __syncthreads();

    // ---- stage 2: z1 @ W2^T (BK=32, B double-buffered) ----
    float c[2][8][4] = {};
    uint2 qb0[2], qb1[2];
#pragma unroll
    for (int j = 0; j < 2; j++) {
        int kc2 = (j * 16 + aks) >> 2;
        qb0[j] = __ldg((const uint2*)(g_W216 + (size_t)am * 128) + kc2);
        qb1[j] = __ldg((const uint2*)(g_W216 + (size_t)(am + 128) * 128) + kc2);
    }
    for (int st = 0; st < 8; st++) {
        int b = st & 1;
        uint32_t* B0 = bufs + b * 2 * BSLAB;
        uint32_t* B1 = B0 + BSLAB;
        store_slab_b(B0, am, k2, qb0[0], qb1[0]);
        store_slab_b(B1, am, k2, qb0[1], qb1[1]);
        uint2 n0[2] = {qb0[0], qb0[1]}, n1[2] = {qb1[0], qb1[1]};
        if (st < 7) {
#pragma unroll
            for (int j = 0; j < 2; j++) {
                int kc2 = ((2 * st + 2 + j) * 16 + aks) >> 2;
                n0[j] = __ldg((const uint2*)(g_W216 + (size_t)am * 128) + kc2);
                n1[j] = __ldg((const uint2*)(g_W216 + (size_t)(am + 128) * 128) + kc2);
            }
        }
        __syncthreads();
        mma_slab(z1sm + (2 * st) * SL, B0, wm, wn, lane, c);
        mma_slab(z1sm + (2 * st + 1) * SL, B1, wm, wn, lane, c);
        qb0[0] = n0[0]; qb0[1] = n0[1];
        qb1[0] = n1[0]; qb1[1] = n1[1];
    }

#pragma unroll
    for (int mt = 0; mt < 2; mt++) {
        float p0 = 0.f, p1 = 0.f;
#pragma unroll
        for (int nt = 0; nt < 8; nt++) {
            int col = wn * 64 + nt * 8 + lr * 2;
            float2 bb = __ldg((const float2*)(b2 + col));
            float2 ww = __ldg((const float2*)(W3 + col));
            p0 = fmaf(fmaxf(c[mt][nt][0] + bb.x, 0.f), ww.x, p0);
            p0 = fmaf(fmaxf(c[mt][nt][1] + bb.y, 0.f), ww.y, p0);
            p1 = fmaf(fmaxf(c[mt][nt][2] + bb.x, 0.f), ww.x, p1);
            p1 = fmaf(fmaxf(c[mt][nt][3] + bb.y, 0.f), ww.y, p1);
        }
        p0 += __shfl_xor_sync(0xffffffffu, p0, 1);
        p0 += __shfl_xor_sync(0xffffffffu, p0, 2);
        p1 += __shfl_xor_sync(0xffffffffu, p1, 1);
        p1 += __shfl_xor_sync(0xffffffffu, p1, 2);
        if (lr == 0) {
            sred[wn][wm * 32 + mt * 16 + lq] = p0;
            sred[wn][wm * 32 + mt * 16 + lq + 8] = p1;
        }
    }
    __syncthreads();
    if (tid < 128) {
        int gr = bm + tid;
        if (gr < N_EDGES) {
            float s = sred[0][tid] + sred[1][tid] + sred[2][tid] + sred[3][tid] + __ldg(b3);
            dout[gr] = 1.f / (1.f + expf(-s));
        }
    }
}

// ---------------------------------------------------------------- launch
extern "C" void kernel_launch(void* const* d_in, const int* in_sizes, int n_in,
                              void* d_out, int out_size) {
    const float* x     = (const float*)d_in[0];
    const int*   ei    = (const int*)  d_in[1];
    const float* Win   = (const float*)d_in[2];
    const float* Wrel  = (const float*)d_in[3];
    const float* brel  = (const float*)d_in[4];
    const float* Wroot = (const float*)d_in[5];
    const float* gamma = (const float*)d_in[6];
    const float* beta  = (const float*)d_in[7];
    const float* W1    = (const float*)d_in[8];
    const float* b1    = (const float*)d_in[9];
    const float* W2    = (const float*)d_in[10];
    const float* b2    = (const float*)d_in[11];
    const float* W3    = (const float*)d_in[12];
    const float* b3    = (const float*)d_in[13];
    float* out = (float*)d_out;

    cudaFuncSetAttribute(k_gemm_node, cudaFuncAttributeMaxDynamicSharedMemorySize, NSMEM);
    cudaFuncSetAttribute(k_gemm_uv,   cudaFuncAttributeMaxDynamicSharedMemorySize, UVSMEM);
    cudaFuncSetAttribute(k_edge_fused, cudaFuncAttributeMaxDynamicSharedMemorySize, ESMEM);

    int ncvt = LAYERS * 256 * 128 + 256 * 256 + 256 * 128;
    k_cvt_weights<<<(ncvt + 255) / 256, 256>>>(Wrel, Wroot, W1, W2);
    k_input_fc<<<(N_NODES * 128 + 255) / 256, 256>>>(x, Win);
    k_csr_count<<<(N_EDGES + 255) / 256, 256>>>(ei);
    int nblk = (N_NODES + 1023) / 1024;   // 49
    k_scan1<<<nblk, 1024>>>();
    k_scan2<<<1, 32>>>(nblk);
    k_scan3<<<(N_NODES + 255) / 256, 256>>>();
    k_csr_fill<<<(N_EDGES + 255) / 256, 256>>>(ei);

    int node_grid = (N_NODES + 127) / 128;     // 391
    for (int l = 0; l < LAYERS; l++) {
        k_gemm_node<<<node_grid, 512, NSMEM>>>(l, brel + (size_t)l * HID);
        k_bn_apply<<<(N_NODES * 32 + 255) / 256, 256>>>(
            l, gamma + (size_t)l * HID, beta + (size_t)l * HID);
    }

    dim3 uv_grid(node_grid, 2);
    k_gemm_uv<<<uv_grid, 512, UVSMEM>>>();
    int edge_grid = (N_EDGES + 127) / 128;     // 3907
    k_edge_fused<<<edge_grid, 512, ESMEM>>>(ei, b1, b2, W3, b3, out);
}